// round 14
// baseline (speedup 1.0000x reference)
#include <cuda_runtime.h>
#include <cuda_bf16.h>
#include <math.h>
#include <cstdint>

#define BATCH   2
#define SEQLEN  512
#define DMODEL  768
#define DINNER  1536
#define NHEADS  24
#define HEADDIM 64
#define DSTATE  128
#define CONVDIM 1792
#define DINPROJ 3352
#define MROWS   (BATCH*SEQLEN)  // 1024
#define LC      64
#define NCHUNK  (SEQLEN/LC)     // 8
#define NBH     (BATCH*NHEADS)  // 48
#define NPAD_IN 3456
#define NSPLIT  6
#define ZXPLANE (MROWS * DINPROJ)
#define INSPLIT 2

// ---------------- scratch ---------------------------------------------------
__device__ float g_zx [INSPLIT * ZXPLANE];   // in-proj partials (2 planes)
__device__ float g_X  [MROWS * DINNER];
__device__ float g_Bm [MROWS * DSTATE];
__device__ float g_Cm [MROWS * DSTATE];
__device__ float g_dtv[NBH * SEQLEN];
__device__ float g_cum[NBH * SEQLEN];
__device__ float g_Y0 [MROWS * DINNER];
__device__ float g_S  [NBH * NCHUNK * HEADDIM * DSTATE];
__device__ float g_P  [NBH * NCHUNK * HEADDIM * DSTATE];
__device__ float g_pp [NSPLIT * MROWS * DMODEL];

__device__ __align__(256) __nv_bfloat16 g_uhi[MROWS * DMODEL],   g_ulo[MROWS * DMODEL];
__device__ __align__(256) __nv_bfloat16 g_wih[NPAD_IN * DMODEL], g_wil[NPAD_IN * DMODEL];
__device__ __align__(256) __nv_bfloat16 g_ghi[MROWS * DINNER],   g_glo[MROWS * DINNER];
__device__ __align__(256) __nv_bfloat16 g_woh[DMODEL * DINNER],  g_wol[DMODEL * DINNER];

// ================= helpers =================================================
__device__ __forceinline__ uint32_t smem_u32(const void* p) {
    uint32_t a;
    asm("{ .reg .u64 t; cvta.to.shared.u64 t, %1; cvt.u32.u64 %0, t; }"
        : "=r"(a) : "l"(p));
    return a;
}
__device__ __forceinline__ void ldsm_x4(uint32_t* r, uint32_t addr) {
    asm volatile("ldmatrix.sync.aligned.m8n8.x4.shared.b16 {%0,%1,%2,%3}, [%4];"
                 : "=r"(r[0]), "=r"(r[1]), "=r"(r[2]), "=r"(r[3]) : "r"(addr));
}
__device__ __forceinline__ void ldsm_x2(uint32_t* r, uint32_t addr) {
    asm volatile("ldmatrix.sync.aligned.m8n8.x2.shared.b16 {%0,%1}, [%2];"
                 : "=r"(r[0]), "=r"(r[1]) : "r"(addr));
}
__device__ __forceinline__ void mma_bf16(float* c, const uint32_t* a, const uint32_t* b) {
    asm volatile(
        "mma.sync.aligned.m16n8k16.row.col.f32.bf16.bf16.f32 "
        "{%0,%1,%2,%3}, {%4,%5,%6,%7}, {%8,%9}, {%0,%1,%2,%3};"
        : "+f"(c[0]), "+f"(c[1]), "+f"(c[2]), "+f"(c[3])
        : "r"(a[0]), "r"(a[1]), "r"(a[2]), "r"(a[3]), "r"(b[0]), "r"(b[1]));
}
__device__ __forceinline__ void split1(float v, __nv_bfloat16& h, __nv_bfloat16& l) {
    h = __float2bfloat16(v);
    l = __float2bfloat16(v - __bfloat162float(h));
}
__device__ __forceinline__ void split2(float2 v, uint32_t& hi2, uint32_t& lo2) {
    __nv_bfloat16 h0, l0, h1, l1;
    split1(v.x, h0, l0);
    split1(v.y, h1, l1);
    __nv_bfloat162 H, L;
    H.x = h0; H.y = h1; L.x = l0; L.y = l1;
    hi2 = *(uint32_t*)&H;
    lo2 = *(uint32_t*)&L;
}
__device__ __forceinline__ void split4_store(float4 v, __nv_bfloat16* hi, __nv_bfloat16* lo, int j) {
    uint32_t h01, l01, h23, l23;
    split2(make_float2(v.x, v.y), h01, l01);
    split2(make_float2(v.z, v.w), h23, l23);
    uint2 H = make_uint2(h01, h23), L = make_uint2(l01, l23);
    *(uint2*)(hi + j) = H;
    *(uint2*)(lo + j) = L;
}

// ================= fused vectorized split of u, W_in(+pad), W_out ==========
#define N_U  (MROWS * DMODEL)
#define N_WI (NPAD_IN * DMODEL)
#define N_WIS (DINPROJ * DMODEL)
#define N_WO (DMODEL * DINNER)
__global__ void split_all_kernel(const float* __restrict__ u,
                                 const float* __restrict__ W_in,
                                 const float* __restrict__ W_out) {
    int i4 = blockIdx.x * blockDim.x + threadIdx.x;
    int i = i4 * 4;
    if (i < N_U) {
        float4 v = *(const float4*)(u + i);
        split4_store(v, g_uhi, g_ulo, i);
    } else if (i < N_U + N_WI) {
        int j = i - N_U;
        float4 v = (j < N_WIS) ? *(const float4*)(W_in + j)
                               : make_float4(0.f, 0.f, 0.f, 0.f);
        split4_store(v, g_wih, g_wil, j);
    } else if (i < N_U + N_WI + N_WO) {
        int j = i - N_U - N_WI;
        float4 v = *(const float4*)(W_out + j);
        split4_store(v, g_woh, g_wol, j);
    }
}

// ================= mma.sync bf16 GEMM, 4-stage pipeline ====================
#define GSTRIDE 24
#define GOP_BYTES (128 * GSTRIDE * 2)      // 6144
#define GSTAGE_BYTES (4 * GOP_BYTES)       // 24576
#define GNSTAGE 4
__global__ __launch_bounds__(256, 2)
void mma_gemm(const __nv_bfloat16* __restrict__ Ahi, const __nv_bfloat16* __restrict__ Alo,
              const __nv_bfloat16* __restrict__ Bhi, const __nv_bfloat16* __restrict__ Blo,
              float* __restrict__ C, int Ktot, int Nact, int ldc, size_t csplit) {
    extern __shared__ char smx[];
    uint32_t sb = smem_u32(smx);
    int tid  = threadIdx.x;
    int lane = tid & 31, wid = tid >> 5;
    int wm = wid >> 2, wn = wid & 3;
    int m0 = blockIdx.y * 128, n0 = blockIdx.x * 128;
    int nsp  = gridDim.z;
    int Klen = Ktot / nsp;
    int k0   = blockIdx.z * Klen;
    float* Cp = C + (size_t)blockIdx.z * csplit;
    const int KT = Klen / 16;

    const __nv_bfloat16* ptrs[4] = {Ahi, Alo, Bhi, Blo};
    int rbase[4] = {m0, m0, n0, n0};

    auto load_stage = [&](int kt, int s) {
        uint32_t sbase = sb + s * GSTAGE_BYTES;
#pragma unroll
        for (int op = 0; op < 4; op++) {
            int r = tid >> 1, hf = tid & 1;
            const void* g = ptrs[op] + (size_t)(rbase[op] + r) * Ktot + k0 + kt * 16 + hf * 8;
            uint32_t d = sbase + op * GOP_BYTES + (r * GSTRIDE + hf * 8) * 2;
            asm volatile("cp.async.cg.shared.global [%0], [%1], 16;" :: "r"(d), "l"(g));
        }
        asm volatile("cp.async.commit_group;");
    };

    float acc[4][4][4];
#pragma unroll
    for (int i = 0; i < 4; i++)
#pragma unroll
        for (int j = 0; j < 4; j++)
#pragma unroll
            for (int q = 0; q < 4; q++) acc[i][j][q] = 0.f;

    load_stage(0, 0);
    load_stage(1, 1);
    load_stage(2, 2);

    for (int kt = 0; kt < KT; kt++) {
        asm volatile("cp.async.wait_group 2;");
        __syncthreads();

        uint32_t st = sb + (kt & 3) * GSTAGE_BYTES;
        uint32_t ah[4][4], al[4][4], bh[4][2], bl[4][2];
        int arow = wm * 64 + (lane & 15);
        int acol = (lane >> 4) * 8;
#pragma unroll
        for (int i = 0; i < 4; i++) {
            uint32_t off = ((arow + i * 16) * GSTRIDE + acol) * 2;
            ldsm_x4(ah[i], st + off);
            ldsm_x4(al[i], st + GOP_BYTES + off);
        }
        int brow = wn * 32 + (lane & 7);
        int bcol = ((lane >> 3) & 1) * 8;
#pragma unroll
        for (int j = 0; j < 4; j++) {
            uint32_t off = ((brow + j * 8) * GSTRIDE + bcol) * 2;
            ldsm_x2(bh[j], st + 2 * GOP_BYTES + off);
            ldsm_x2(bl[j], st + 3 * GOP_BYTES + off);
        }
#pragma unroll
        for (int i = 0; i < 4; i++)
#pragma unroll
            for (int j = 0; j < 4; j++) {
                mma_bf16(acc[i][j], ah[i], bh[j]);
                mma_bf16(acc[i][j], ah[i], bl[j]);
                mma_bf16(acc[i][j], al[i], bh[j]);
            }

        if (kt + 3 < KT) load_stage(kt + 3, (kt + 3) & 3);
        else             asm volatile("cp.async.commit_group;");
    }

    int r0 = m0 + wm * 64 + (lane >> 2);
    int c0 = n0 + wn * 32 + (lane & 3) * 2;
#pragma unroll
    for (int i = 0; i < 4; i++) {
#pragma unroll
        for (int j = 0; j < 4; j++) {
            int rr = r0 + i * 16;
            int cc = c0 + j * 8;
            if (cc < Nact)     Cp[(size_t)rr * ldc + cc]           = acc[i][j][0];
            if (cc + 1 < Nact) Cp[(size_t)rr * ldc + cc + 1]       = acc[i][j][1];
            if (cc < Nact)     Cp[(size_t)(rr + 8) * ldc + cc]     = acc[i][j][2];
            if (cc + 1 < Nact) Cp[(size_t)(rr + 8) * ldc + cc + 1] = acc[i][j][3];
        }
    }
}

// ---------------- reduce NSPLIT partials -> out -----------------------------
__global__ void reduce_kernel(float* __restrict__ out) {
    int i = blockIdx.x * blockDim.x + threadIdx.x;
    const int n4 = MROWS * DMODEL / 4;
    if (i >= n4) return;
    float4 r = make_float4(0.f, 0.f, 0.f, 0.f);
#pragma unroll
    for (int s = 0; s < NSPLIT; s++) {
        float4 a = *(const float4*)(g_pp + (size_t)s * MROWS * DMODEL + i * 4);
        r.x += a.x; r.y += a.y; r.z += a.z; r.w += a.w;
    }
    *(float4*)(out + i * 4) = r;
}

// ---------------- fused: vectorized conv+SiLU  AND  dt/cumsum ---------------
// blocks [0, CONV_BLOCKS): conv, one thread = 4 channels (float4).
// blocks [CONV_BLOCKS, +DT_BLOCKS): dtcum, 256 thr = 4 chunks of 64.
#define CONV_ELEM4 (MROWS * CONVDIM / 4)         // 458752
#define CONV_BLOCKS ((CONV_ELEM4 + 255) / 256)   // 1792
#define DT_BLOCKS (NBH * NCHUNK / 4)             // 96
__global__ void conv_dt_kernel(const float* __restrict__ conv_w,
                               const float* __restrict__ conv_b,
                               const float* __restrict__ dt_bias,
                               const float* __restrict__ A_log) {
    if (blockIdx.x < CONV_BLOCKS) {
        int idx4 = blockIdx.x * 256 + threadIdx.x;
        if (idx4 >= CONV_ELEM4) return;
        int c4 = (idx4 % (CONVDIM / 4)) * 4;
        int m  = idx4 / (CONVDIM / 4);
        int t  = m % SEQLEN;
        float4 s = *(const float4*)(conv_b + c4);
#pragma unroll
        for (int k = 0; k < 4; k++) {
            int tt = t - 3 + k;
            if (tt >= 0) {
                size_t o = (size_t)(m - 3 + k) * DINPROJ + DINNER + c4;
                float4 z0 = *(const float4*)(g_zx + o);
                float4 z1 = *(const float4*)(g_zx + o + ZXPLANE);
                // weights: conv_w[c][k] layout, gather 4 channels at tap k
                float w0 = conv_w[(c4 + 0) * 4 + k];
                float w1 = conv_w[(c4 + 1) * 4 + k];
                float w2 = conv_w[(c4 + 2) * 4 + k];
                float w3 = conv_w[(c4 + 3) * 4 + k];
                s.x += (z0.x + z1.x) * w0;
                s.y += (z0.y + z1.y) * w1;
                s.z += (z0.z + z1.z) * w2;
                s.w += (z0.w + z1.w) * w3;
            }
        }
        float4 v;
        v.x = s.x / (1.f + expf(-s.x));
        v.y = s.y / (1.f + expf(-s.y));
        v.z = s.z / (1.f + expf(-s.z));
        v.w = s.w / (1.f + expf(-s.w));
        if (c4 < DINNER)
            *(float4*)(g_X + m * DINNER + c4) = v;
        else if (c4 < DINNER + DSTATE)
            *(float4*)(g_Bm + m * DSTATE + (c4 - DINNER)) = v;
        else
            *(float4*)(g_Cm + m * DSTATE + (c4 - DINNER - DSTATE)) = v;
    } else {
        // dtcum: 4 chunks per block
        __shared__ float w0tot[4];
        int sub = threadIdx.x >> 6;      // 0..3
        int t   = threadIdx.x & 63;
        int g   = (blockIdx.x - CONV_BLOCKS) * 4 + sub;
        int c   = g & (NCHUNK - 1);
        int bh  = g >> 3;
        int h   = bh % NHEADS;
        int b   = bh / NHEADS;
        int m   = b * SEQLEN + c * LC + t;

        size_t o = (size_t)m * DINPROJ + DINNER + CONVDIM + h;
        float x   = g_zx[o] + g_zx[o + ZXPLANE] + dt_bias[h];
        float dtv = (x > 20.f) ? x : log1pf(expf(x));
        float a   = -expf(A_log[h]) * dtv;

        float sc = a;
#pragma unroll
        for (int o2 = 1; o2 < 32; o2 <<= 1) {
            float v = __shfl_up_sync(0xffffffffu, sc, o2);
            if ((t & 31) >= o2) sc += v;
        }
        if (t == 31) w0tot[sub] = sc;
        __syncthreads();
        if (t >= 32) sc += w0tot[sub];

        int idx = bh * SEQLEN + c * LC + t;
        g_dtv[idx] = dtv;
        g_cum[idx] = sc;
    }
}

// ---------------- intra-chunk kernel (tensor cores, smem-compacted) --------
#define OFF_SCUM 0
#define OFF_SDT  256
#define OFF_SW   512
#define PLANE128 (64*136*2)     // 17408
#define PLANE64  (64*72*2)      // 9216
#define PLANE128T (128*72*2)    // 18432
#define OFF_XTHI 768
#define OFF_XTLO (OFF_XTHI + PLANE64)
#define OFF_BIG  (OFF_XTLO + PLANE64)        // 19200
#define OFF_CHI  (OFF_BIG)
#define OFF_CLO  (OFF_CHI + PLANE128)
#define OFF_BHI  (OFF_CLO + PLANE128)
#define OFF_BLO  (OFF_BHI + PLANE128)
#define OFF_GHI  (OFF_BIG)
#define OFF_GLO  (OFF_GHI + PLANE64)
#define OFF_BWHI (OFF_GLO + PLANE64)
#define OFF_BWLO (OFF_BWHI + PLANE128T)
#define INTRA_SMEM (OFF_BIG + 4*PLANE128)    // 88832
__global__ __launch_bounds__(256, 2)
void intra_tc(const float* __restrict__ D_param) {
    extern __shared__ char smc[];
    uint32_t sb = smem_u32(smc);
    float* scum = (float*)(smc + OFF_SCUM);
    float* sdt  = (float*)(smc + OFF_SDT);
    float* sw   = (float*)(smc + OFF_SW);
    __nv_bfloat16* Xthi = (__nv_bfloat16*)(smc + OFF_XTHI);
    __nv_bfloat16* Xtlo = (__nv_bfloat16*)(smc + OFF_XTLO);
    __nv_bfloat16* Bwhi = (__nv_bfloat16*)(smc + OFF_BWHI);
    __nv_bfloat16* Bwlo = (__nv_bfloat16*)(smc + OFF_BWLO);
    __nv_bfloat16* Ghi  = (__nv_bfloat16*)(smc + OFF_GHI);
    __nv_bfloat16* Glo  = (__nv_bfloat16*)(smc + OFF_GLO);

    int g  = blockIdx.x;
    int c  = g & (NCHUNK - 1);
    int bh = g >> 3;
    int h  = bh % NHEADS;
    int b  = bh / NHEADS;
    int tid = threadIdx.x;
    int lane = tid & 31, wid = tid >> 5;
    int m0 = b * SEQLEN + c * LC;

    if (tid < 64) {
        scum[tid] = g_cum[bh * SEQLEN + c * LC + tid];
        sdt[tid]  = g_dtv[bh * SEQLEN + c * LC + tid];
    }
    for (int i = tid; i < 64 * 64; i += 256) {
        int r = i >> 6, q = (i & 63) * 2;
        float2 vc = *(const float2*)(g_Cm + (size_t)(m0 + r) * DSTATE + q);
        float2 vb = *(const float2*)(g_Bm + (size_t)(m0 + r) * DSTATE + q);
        uint32_t h2, l2;
        split2(vc, h2, l2);
        *(uint32_t*)(smc + OFF_CHI + (r * 136 + q) * 2) = h2;
        *(uint32_t*)(smc + OFF_CLO + (r * 136 + q) * 2) = l2;
        split2(vb, h2, l2);
        *(uint32_t*)(smc + OFF_BHI + (r * 136 + q) * 2) = h2;
        *(uint32_t*)(smc + OFF_BLO + (r * 136 + q) * 2) = l2;
    }
    for (int i = tid; i < 64 * 16; i += 256) {
        int t_ = i >> 4, p4 = (i & 15) * 4;
        float4 v = *(const float4*)(g_X + (size_t)(m0 + t_) * DINNER + h * HEADDIM + p4);
        float vv[4] = {v.x, v.y, v.z, v.w};
#pragma unroll
        for (int e = 0; e < 4; e++) {
            __nv_bfloat16 hh, ll;
            split1(vv[e], hh, ll);
            Xthi[(p4 + e) * 72 + t_] = hh;
            Xtlo[(p4 + e) * 72 + t_] = ll;
        }
    }
    __syncthreads();
    if (tid < 64) sw[tid] = expf(scum[63] - scum[tid]) * sdt[tid];
    __syncthreads();

    int wm = wid & 3, wn = wid >> 2;
    int brow8 = ((lane >> 4) & 1) * 8 + (lane & 7);
    int bcolb = ((lane >> 3) & 1) * 8;

    // ---- stage 1: G0 = C . B^T ----
    float acc1[4][4] = {};
    {
        for (int kk = 0; kk < 8; kk++) {
            uint32_t ah[4], al[4], bh2[4][2], bl2[4][2];
            int arow = wm * 16 + (lane & 15);
            int acol = (lane >> 4) * 8 + kk * 16;
            ldsm_x4(ah, sb + OFF_CHI + (arow * 136 + acol) * 2);
            ldsm_x4(al, sb + OFF_CLO + (arow * 136 + acol) * 2);
            int bcol = bcolb + kk * 16;
#pragma unroll
            for (int j2 = 0; j2 < 2; j2++) {
                int br = wn * 32 + j2 * 16 + brow8;
                ldsm_x4(&bh2[2 * j2][0], sb + OFF_BHI + (br * 136 + bcol) * 2);
                ldsm_x4(&bl2[2 * j2][0], sb + OFF_BLO + (br * 136 + bcol) * 2);
            }
#pragma unroll
            for (int j = 0; j < 4; j++) {
                mma_bf16(acc1[j], ah, bh2[j]);
                mma_bf16(acc1[j], ah, bl2[j]);
                mma_bf16(acc1[j], al, bh2[j]);
            }
        }
    }
    __syncthreads();

    {
        int tr = wm * 16 + (lane >> 2);
#pragma unroll
        for (int j = 0; j < 4; j++) {
            int sc0 = wn * 32 + j * 8 + (lane & 3) * 2;
#pragma unroll
            for (int hlf = 0; hlf < 2; hlf++) {
                int t_ = tr + hlf * 8;
#pragma unroll
                for (int e = 0; e < 2; e++) {
                    int s_ = sc0 + e;
                    float wgt = (s_ <= t_) ? expf(scum[t_] - scum[s_]) * sdt[s_] : 0.f;
                    float gv = acc1[j][hlf * 2 + e] * wgt;
                    __nv_bfloat16 hh, ll;
                    split1(gv, hh, ll);
                    Ghi[t_ * 72 + s_] = hh;
                    Glo[t_ * 72 + s_] = ll;
                }
            }
        }
    }
    for (int i = tid; i < 64 * 32; i += 256) {
        int s_ = i >> 5, n4 = (i & 31) * 4;
        float4 v = *(const float4*)(g_Bm + (size_t)(m0 + s_) * DSTATE + n4);
        float w = sw[s_];
        float vv[4] = {v.x * w, v.y * w, v.z * w, v.w * w};
#pragma unroll
        for (int e = 0; e < 4; e++) {
            __nv_bfloat16 hh, ll;
            split1(vv[e], hh, ll);
            Bwhi[(n4 + e) * 72 + s_] = hh;
            Bwlo[(n4 + e) * 72 + s_] = ll;
        }
    }
    __syncthreads();

    // ---- stage 2: Y = G . Xt^T (+ D*x) ----
    {
        float acc[4][4] = {};
        for (int kk = 0; kk < 4; kk++) {
            uint32_t ah[4], al[4], bh2[4][2], bl2[4][2];
            int arow = wm * 16 + (lane & 15);
            int acol = (lane >> 4) * 8 + kk * 16;
            ldsm_x4(ah, sb + OFF_GHI + (arow * 72 + acol) * 2);
            ldsm_x4(al, sb + OFF_GLO + (arow * 72 + acol) * 2);
            int bcol = bcolb + kk * 16;
#pragma unroll
            for (int j2 = 0; j2 < 2; j2++) {
                int br = wn * 32 + j2 * 16 + brow8;
                ldsm_x4(&bh2[2 * j2][0], sb + OFF_XTHI + (br * 72 + bcol) * 2);
                ldsm_x4(&bl2[2 * j2][0], sb + OFF_XTLO + (br * 72 + bcol) * 2);
            }
#pragma unroll
            for (int j = 0; j < 4; j++) {
                mma_bf16(acc[j], ah, bh2[j]);
                mma_bf16(acc[j], ah, bl2[j]);
                mma_bf16(acc[j], al, bh2[j]);
            }
        }
        float Dp = D_param[h];
        int tr = wm * 16 + (lane >> 2);
#pragma unroll
        for (int j = 0; j < 4; j++) {
            int p0 = wn * 32 + j * 8 + (lane & 3) * 2;
#pragma unroll
            for (int hlf = 0; hlf < 2; hlf++) {
                int t_ = tr + hlf * 8;
#pragma unroll
                for (int e = 0; e < 2; e++) {
                    int p_ = p0 + e;
                    float xv = __bfloat162float(Xthi[p_ * 72 + t_])
                             + __bfloat162float(Xtlo[p_ * 72 + t_]);
                    g_Y0[(size_t)(m0 + t_) * DINNER + h * HEADDIM + p_] =
                        acc[j][hlf * 2 + e] + Dp * xv;
                }
            }
        }
    }

    // ---- stage 3: S = Xt . Bwt^T ----
    {
        float acc[8][4] = {};
        for (int kk = 0; kk < 4; kk++) {
            uint32_t ah[4], al[4], bh2[8][2], bl2[8][2];
            int arow = wm * 16 + (lane & 15);
            int acol = (lane >> 4) * 8 + kk * 16;
            ldsm_x4(ah, sb + OFF_XTHI + (arow * 72 + acol) * 2);
            ldsm_x4(al, sb + OFF_XTLO + (arow * 72 + acol) * 2);
            int bcol = bcolb + kk * 16;
#pragma unroll
            for (int j2 = 0; j2 < 4; j2++) {
                int br = wn * 64 + j2 * 16 + brow8;
                ldsm_x4(&bh2[2 * j2][0], sb + OFF_BWHI + (br * 72 + bcol) * 2);
                ldsm_x4(&bl2[2 * j2][0], sb + OFF_BWLO + (br * 72 + bcol) * 2);
            }
#pragma unroll
            for (int j = 0; j < 8; j++) {
                mma_bf16(acc[j], ah, bh2[j]);
                mma_bf16(acc[j], ah, bl2[j]);
                mma_bf16(acc[j], al, bh2[j]);
            }
        }
        size_t base = (size_t)(bh * NCHUNK + c) * (HEADDIM * DSTATE);
        int pr = wm * 16 + (lane >> 2);
#pragma unroll
        for (int j = 0; j < 8; j++) {
            int n0_ = wn * 64 + j * 8 + (lane & 3) * 2;
#pragma unroll
            for (int hlf = 0; hlf < 2; hlf++) {
                int p_ = pr + hlf * 8;
#pragma unroll
                for (int e = 0; e < 2; e++) {
                    g_S[base + p_ * DSTATE + n0_ + e] = acc[j][hlf * 2 + e];
                }
            }
        }
    }
}

// ---------------- inter-chunk state scan: 192 blocks, 1 float4/thread -------
__global__ void chunkscan_kernel() {
    int bh   = blockIdx.x >> 2;
    int part = blockIdx.x & 3;
    int idx4 = part * 2048 + threadIdx.x * 4;
    float4 E = make_float4(0.f, 0.f, 0.f, 0.f);
    size_t base = (size_t)bh * NCHUNK * (HEADDIM * DSTATE);
#pragma unroll
    for (int k = 0; k < NCHUNK; k++) {
        float dAk = expf(g_cum[bh * SEQLEN + k * LC + (LC - 1)]);
        size_t off = base + (size_t)k * (HEADDIM * DSTATE) + idx4;
        *(float4*)(g_P + off) = E;
        float4 s = *(const float4*)(g_S + off);
        E.x = s.x + dAk * E.x;
        E.y = s.y + dAk * E.y;
        E.z = s.z + dAk * E.z;
        E.w = s.w + dAk * E.w;
    }
}

// ---------------- inter-chunk Y + gating + bf16 split -----------------------
#define SB_STRIDE 132
#define SMEMD_FLOATS (2*64*SB_STRIDE + 64)
__global__ __launch_bounds__(256)
void inter_gate_kernel() {
    extern __shared__ float sm[];
    float* sC   = sm;
    float* sP   = sC + 64 * SB_STRIDE;
    float* scum = sP + 64 * SB_STRIDE;

    int g  = blockIdx.x;
    int c  = g & (NCHUNK - 1);
    int bh = g >> 3;
    int h  = bh % NHEADS;
    int b  = bh / NHEADS;
    int tid = threadIdx.x;
    int m0 = b * SEQLEN + c * LC;
    size_t pbase = (size_t)(bh * NCHUNK + c) * (HEADDIM * DSTATE);

    for (int i = tid; i < 64 * 32; i += 256) {
        int r = i >> 5, q = i & 31;
        *(float4*)(sC + r * SB_STRIDE + q * 4) =
            *(const float4*)(g_Cm + (size_t)(m0 + r) * DSTATE + q * 4);
        *(float4*)(sP + r * SB_STRIDE + q * 4) =
            *(const float4*)(g_P + pbase + r * DSTATE + q * 4);
    }
    if (tid < 64) scum[tid] = g_cum[bh * SEQLEN + c * LC + tid];
    __syncthreads();

    int tx = tid & 15, ty = tid >> 4;
    int rot = (tid & 15) * 4;
    float acc[4][4] = {};
    for (int n0_ = 0; n0_ < 128; n0_ += 4) {
        int n = (n0_ + rot) & 127;
        float4 a4[4], b4[4];
#pragma unroll
        for (int i = 0; i < 4; i++) a4[i] = *(float4*)(sC + (ty * 4 + i) * SB_STRIDE + n);
#pragma unroll
        for (int j = 0; j < 4; j++) b4[j] = *(float4*)(sP + (tx * 4 + j) * SB_STRIDE + n);
#pragma unroll
        for (int i = 0; i < 4; i++)
#pragma unroll
            for (int j = 0; j < 4; j++)
                acc[i][j] += a4[i].x * b4[j].x + a4[i].y * b4[j].y
                           + a4[i].z * b4[j].z + a4[i].w * b4[j].w;
    }
#pragma unroll
    for (int i = 0; i < 4; i++) {
        int t_ = ty * 4 + i;
        float dec = expf(scum[t_]);
#pragma unroll
        for (int j = 0; j < 4; j++) {
            int p_ = tx * 4 + j;
            size_t mi = (size_t)(m0 + t_) * DINNER + h * HEADDIM + p_;
            float y = g_Y0[mi] + dec * acc[i][j];
            size_t zo = (size_t)(m0 + t_) * DINPROJ + h * HEADDIM + p_;
            float z = g_zx[zo] + g_zx[zo + ZXPLANE];
            float gv = y * (z / (1.f + expf(-z)));
            __nv_bfloat16 hb, lb;
            split1(gv, hb, lb);
            g_ghi[mi] = hb;
            g_glo[mi] = lb;
        }
    }
}

// ---------------- launch ----------------------------------------------------
extern "C" void kernel_launch(void* const* d_in, const int* in_sizes, int n_in,
                              void* d_out, int out_size) {
    const float* u       = (const float*)d_in[0];
    const float* W_in    = (const float*)d_in[1];
    const float* conv_w  = (const float*)d_in[2];
    const float* conv_b  = (const float*)d_in[3];
    const float* dt_bias = (const float*)d_in[4];
    const float* A_log   = (const float*)d_in[5];
    const float* D_param = (const float*)d_in[6];
    const float* W_out   = (const float*)d_in[7];
    float* out = (float*)d_out;

    float *zx, *pp;
    cudaGetSymbolAddress((void**)&zx, g_zx);
    cudaGetSymbolAddress((void**)&pp, g_pp);
    __nv_bfloat16 *uhi, *ulo, *wih, *wil, *ghi, *glo, *woh, *wol;
    cudaGetSymbolAddress((void**)&uhi, g_uhi);  cudaGetSymbolAddress((void**)&ulo, g_ulo);
    cudaGetSymbolAddress((void**)&wih, g_wih);  cudaGetSymbolAddress((void**)&wil, g_wil);
    cudaGetSymbolAddress((void**)&ghi, g_ghi);  cudaGetSymbolAddress((void**)&glo, g_glo);
    cudaGetSymbolAddress((void**)&woh, g_woh);  cudaGetSymbolAddress((void**)&wol, g_wol);

    static bool attr_done = false;
    if (!attr_done) {
        cudaFuncSetAttribute(intra_tc, cudaFuncAttributeMaxDynamicSharedMemorySize,
                             INTRA_SMEM);
        cudaFuncSetAttribute(inter_gate_kernel, cudaFuncAttributeMaxDynamicSharedMemorySize,
                             SMEMD_FLOATS * sizeof(float));
        cudaFuncSetAttribute(mma_gemm, cudaFuncAttributeMaxDynamicSharedMemorySize,
                             GNSTAGE * GSTAGE_BYTES);
        attr_done = true;
    }
    const int TC_SMEM = GNSTAGE * GSTAGE_BYTES;  // 98304

    // 0. fused vectorized split of u, W_in, W_out
    {
        int ntot4 = (N_U + N_WI + N_WO) / 4;
        split_all_kernel<<<(ntot4 + 255) / 256, 256>>>(u, W_in, W_out);
    }
    // 1. in-projection, split-K x2 (consumers fuse the reduction)
    {
        dim3 grid(NPAD_IN / 128, MROWS / 128, INSPLIT);
        mma_gemm<<<grid, 256, TC_SMEM>>>(uhi, ulo, wih, wil, zx,
                                         DMODEL, DINPROJ, DINPROJ, (size_t)ZXPLANE);
    }
    // 2+3. fused conv+silu and dt+cumsum (independent, run concurrently)
    conv_dt_kernel<<<CONV_BLOCKS + DT_BLOCKS, 256>>>(conv_w, conv_b, dt_bias, A_log);
    // 4. intra-chunk (tensor cores)
    intra_tc<<<NBH * NCHUNK, 256, INTRA_SMEM>>>(D_param);
    // 5. inter-chunk state scan
    chunkscan_kernel<<<NBH * 4, 512>>>();
    // 6. inter-chunk Y + gating (sums 2 zx planes)
    inter_gate_kernel<<<NBH * NCHUNK, 256, SMEMD_FLOATS * sizeof(float)>>>();
    // 7. out-projection, split-K x6, then reduce
    {
        dim3 grid(DMODEL / 128, MROWS / 128, NSPLIT);
        mma_gemm<<<grid, 256, TC_SMEM>>>(ghi, glo, woh, wol, pp,
                                         DINNER, DMODEL, DMODEL,
                                         (size_t)MROWS * DMODEL);
        reduce_kernel<<<(MROWS * DMODEL / 4 + 255) / 256, 256>>>(out);
    }
}

// round 15
// speedup vs baseline: 1.0990x; 1.0990x over previous
#include <cuda_runtime.h>
#include <cuda_bf16.h>
#include <math.h>
#include <cstdint>

#define BATCH   2
#define SEQLEN  512
#define DMODEL  768
#define DINNER  1536
#define NHEADS  24
#define HEADDIM 64
#define DSTATE  128
#define CONVDIM 1792
#define DINPROJ 3352
#define MROWS   (BATCH*SEQLEN)  // 1024
#define LC      64
#define NCHUNK  (SEQLEN/LC)     // 8
#define NBH     (BATCH*NHEADS)  // 48
#define NPAD_IN 3456
#define NSPLIT  6
#define ZXPLANE (MROWS * DINPROJ)
#define INSPLIT 2

// ---------------- scratch ---------------------------------------------------
__device__ float g_zx [INSPLIT * ZXPLANE];   // in-proj partials (2 planes)
__device__ float g_X  [MROWS * DINNER];
__device__ float g_Bm [MROWS * DSTATE];
__device__ float g_Cm [MROWS * DSTATE];
__device__ float g_dtv[NBH * SEQLEN];
__device__ float g_cum[NBH * SEQLEN];
__device__ float g_Y0 [MROWS * DINNER];
__device__ float g_S  [NBH * NCHUNK * HEADDIM * DSTATE];
__device__ float g_P  [NBH * NCHUNK * HEADDIM * DSTATE];
__device__ float g_pp [NSPLIT * MROWS * DMODEL];

__device__ __align__(256) __nv_bfloat16 g_uhi[MROWS * DMODEL],   g_ulo[MROWS * DMODEL];
__device__ __align__(256) __nv_bfloat16 g_wih[NPAD_IN * DMODEL], g_wil[NPAD_IN * DMODEL];
__device__ __align__(256) __nv_bfloat16 g_ghi[MROWS * DINNER],   g_glo[MROWS * DINNER];
__device__ __align__(256) __nv_bfloat16 g_woh[DMODEL * DINNER],  g_wol[DMODEL * DINNER];

// ================= helpers =================================================
__device__ __forceinline__ uint32_t smem_u32(const void* p) {
    uint32_t a;
    asm("{ .reg .u64 t; cvta.to.shared.u64 t, %1; cvt.u32.u64 %0, t; }"
        : "=r"(a) : "l"(p));
    return a;
}
__device__ __forceinline__ void ldsm_x4(uint32_t* r, uint32_t addr) {
    asm volatile("ldmatrix.sync.aligned.m8n8.x4.shared.b16 {%0,%1,%2,%3}, [%4];"
                 : "=r"(r[0]), "=r"(r[1]), "=r"(r[2]), "=r"(r[3]) : "r"(addr));
}
__device__ __forceinline__ void ldsm_x2(uint32_t* r, uint32_t addr) {
    asm volatile("ldmatrix.sync.aligned.m8n8.x2.shared.b16 {%0,%1}, [%2];"
                 : "=r"(r[0]), "=r"(r[1]) : "r"(addr));
}
__device__ __forceinline__ void mma_bf16(float* c, const uint32_t* a, const uint32_t* b) {
    asm volatile(
        "mma.sync.aligned.m16n8k16.row.col.f32.bf16.bf16.f32 "
        "{%0,%1,%2,%3}, {%4,%5,%6,%7}, {%8,%9}, {%0,%1,%2,%3};"
        : "+f"(c[0]), "+f"(c[1]), "+f"(c[2]), "+f"(c[3])
        : "r"(a[0]), "r"(a[1]), "r"(a[2]), "r"(a[3]), "r"(b[0]), "r"(b[1]));
}
__device__ __forceinline__ void split1(float v, __nv_bfloat16& h, __nv_bfloat16& l) {
    h = __float2bfloat16(v);
    l = __float2bfloat16(v - __bfloat162float(h));
}
__device__ __forceinline__ void split2(float2 v, uint32_t& hi2, uint32_t& lo2) {
    __nv_bfloat16 h0, l0, h1, l1;
    split1(v.x, h0, l0);
    split1(v.y, h1, l1);
    __nv_bfloat162 H, L;
    H.x = h0; H.y = h1; L.x = l0; L.y = l1;
    hi2 = *(uint32_t*)&H;
    lo2 = *(uint32_t*)&L;
}
__device__ __forceinline__ void split4_store(float4 v, __nv_bfloat16* hi, __nv_bfloat16* lo, int j) {
    uint32_t h01, l01, h23, l23;
    split2(make_float2(v.x, v.y), h01, l01);
    split2(make_float2(v.z, v.w), h23, l23);
    uint2 H = make_uint2(h01, h23), L = make_uint2(l01, l23);
    *(uint2*)(hi + j) = H;
    *(uint2*)(lo + j) = L;
}

// ================= fused vectorized split of u, W_in(+pad), W_out ==========
#define N_U  (MROWS * DMODEL)
#define N_WI (NPAD_IN * DMODEL)
#define N_WIS (DINPROJ * DMODEL)
#define N_WO (DMODEL * DINNER)
__global__ void split_all_kernel(const float* __restrict__ u,
                                 const float* __restrict__ W_in,
                                 const float* __restrict__ W_out) {
    int i4 = blockIdx.x * blockDim.x + threadIdx.x;
    int i = i4 * 4;
    if (i < N_U) {
        float4 v = *(const float4*)(u + i);
        split4_store(v, g_uhi, g_ulo, i);
    } else if (i < N_U + N_WI) {
        int j = i - N_U;
        float4 v = (j < N_WIS) ? *(const float4*)(W_in + j)
                               : make_float4(0.f, 0.f, 0.f, 0.f);
        split4_store(v, g_wih, g_wil, j);
    } else if (i < N_U + N_WI + N_WO) {
        int j = i - N_U - N_WI;
        float4 v = *(const float4*)(W_out + j);
        split4_store(v, g_woh, g_wol, j);
    }
}

// ================= mma.sync bf16 GEMM, 4-stage pipeline ====================
#define GSTRIDE 24
#define GOP_BYTES (128 * GSTRIDE * 2)      // 6144
#define GSTAGE_BYTES (4 * GOP_BYTES)       // 24576
#define GNSTAGE 4
__global__ __launch_bounds__(256, 2)
void mma_gemm(const __nv_bfloat16* __restrict__ Ahi, const __nv_bfloat16* __restrict__ Alo,
              const __nv_bfloat16* __restrict__ Bhi, const __nv_bfloat16* __restrict__ Blo,
              float* __restrict__ C, int Ktot, int Nact, int ldc, size_t csplit) {
    extern __shared__ char smx[];
    uint32_t sb = smem_u32(smx);
    int tid  = threadIdx.x;
    int lane = tid & 31, wid = tid >> 5;
    int wm = wid >> 2, wn = wid & 3;
    int m0 = blockIdx.y * 128, n0 = blockIdx.x * 128;
    int nsp  = gridDim.z;
    int Klen = Ktot / nsp;
    int k0   = blockIdx.z * Klen;
    float* Cp = C + (size_t)blockIdx.z * csplit;
    const int KT = Klen / 16;

    const __nv_bfloat16* ptrs[4] = {Ahi, Alo, Bhi, Blo};
    int rbase[4] = {m0, m0, n0, n0};

    auto load_stage = [&](int kt, int s) {
        uint32_t sbase = sb + s * GSTAGE_BYTES;
#pragma unroll
        for (int op = 0; op < 4; op++) {
            int r = tid >> 1, hf = tid & 1;
            const void* g = ptrs[op] + (size_t)(rbase[op] + r) * Ktot + k0 + kt * 16 + hf * 8;
            uint32_t d = sbase + op * GOP_BYTES + (r * GSTRIDE + hf * 8) * 2;
            asm volatile("cp.async.cg.shared.global [%0], [%1], 16;" :: "r"(d), "l"(g));
        }
        asm volatile("cp.async.commit_group;");
    };

    float acc[4][4][4];
#pragma unroll
    for (int i = 0; i < 4; i++)
#pragma unroll
        for (int j = 0; j < 4; j++)
#pragma unroll
            for (int q = 0; q < 4; q++) acc[i][j][q] = 0.f;

    load_stage(0, 0);
    load_stage(1, 1);
    load_stage(2, 2);

    for (int kt = 0; kt < KT; kt++) {
        asm volatile("cp.async.wait_group 2;");
        __syncthreads();

        uint32_t st = sb + (kt & 3) * GSTAGE_BYTES;
        uint32_t ah[4][4], al[4][4], bh[4][2], bl[4][2];
        int arow = wm * 64 + (lane & 15);
        int acol = (lane >> 4) * 8;
#pragma unroll
        for (int i = 0; i < 4; i++) {
            uint32_t off = ((arow + i * 16) * GSTRIDE + acol) * 2;
            ldsm_x4(ah[i], st + off);
            ldsm_x4(al[i], st + GOP_BYTES + off);
        }
        int brow = wn * 32 + (lane & 7);
        int bcol = ((lane >> 3) & 1) * 8;
#pragma unroll
        for (int j = 0; j < 4; j++) {
            uint32_t off = ((brow + j * 8) * GSTRIDE + bcol) * 2;
            ldsm_x2(bh[j], st + 2 * GOP_BYTES + off);
            ldsm_x2(bl[j], st + 3 * GOP_BYTES + off);
        }
#pragma unroll
        for (int i = 0; i < 4; i++)
#pragma unroll
            for (int j = 0; j < 4; j++) {
                mma_bf16(acc[i][j], ah[i], bh[j]);
                mma_bf16(acc[i][j], ah[i], bl[j]);
                mma_bf16(acc[i][j], al[i], bh[j]);
            }

        if (kt + 3 < KT) load_stage(kt + 3, (kt + 3) & 3);
        else             asm volatile("cp.async.commit_group;");
    }

    int r0 = m0 + wm * 64 + (lane >> 2);
    int c0 = n0 + wn * 32 + (lane & 3) * 2;
#pragma unroll
    for (int i = 0; i < 4; i++) {
#pragma unroll
        for (int j = 0; j < 4; j++) {
            int rr = r0 + i * 16;
            int cc = c0 + j * 8;
            if (cc < Nact)     Cp[(size_t)rr * ldc + cc]           = acc[i][j][0];
            if (cc + 1 < Nact) Cp[(size_t)rr * ldc + cc + 1]       = acc[i][j][1];
            if (cc < Nact)     Cp[(size_t)(rr + 8) * ldc + cc]     = acc[i][j][2];
            if (cc + 1 < Nact) Cp[(size_t)(rr + 8) * ldc + cc + 1] = acc[i][j][3];
        }
    }
}

// ---------------- reduce NSPLIT partials -> out -----------------------------
__global__ void reduce_kernel(float* __restrict__ out) {
    int i = blockIdx.x * blockDim.x + threadIdx.x;
    const int n4 = MROWS * DMODEL / 4;
    if (i >= n4) return;
    float4 r = make_float4(0.f, 0.f, 0.f, 0.f);
#pragma unroll
    for (int s = 0; s < NSPLIT; s++) {
        float4 a = *(const float4*)(g_pp + (size_t)s * MROWS * DMODEL + i * 4);
        r.x += a.x; r.y += a.y; r.z += a.z; r.w += a.w;
    }
    *(float4*)(out + i * 4) = r;
}

// ---------------- causal depthwise conv + SiLU (sums 2 zx planes) ----------
__global__ void conv_kernel(const float* __restrict__ conv_w,
                            const float* __restrict__ conv_b) {
    int idx = blockIdx.x * blockDim.x + threadIdx.x;
    if (idx >= MROWS * CONVDIM) return;
    int c = idx % CONVDIM;
    int m = idx / CONVDIM;
    int t = m % SEQLEN;
    float s = conv_b[c];
#pragma unroll
    for (int k = 0; k < 4; k++) {
        int tt = t - 3 + k;
        if (tt >= 0) {
            size_t o = (size_t)(m - 3 + k) * DINPROJ + DINNER + c;
            s += (g_zx[o] + g_zx[o + ZXPLANE]) * conv_w[c * 4 + k];
        }
    }
    float v = s / (1.f + expf(-s));
    if (c < DINNER)                g_X [m * DINNER + c] = v;
    else if (c < DINNER + DSTATE)  g_Bm[m * DSTATE + (c - DINNER)] = v;
    else                           g_Cm[m * DSTATE + (c - DINNER - DSTATE)] = v;
}

// ---------------- dt = softplus, within-chunk cumsum of dt*A ---------------
__global__ void dtcum_kernel(const float* __restrict__ dt_bias,
                             const float* __restrict__ A_log) {
    int g  = blockIdx.x;
    int c  = g & (NCHUNK - 1);
    int bh = g >> 3;
    int h  = bh % NHEADS;
    int b  = bh / NHEADS;
    int t  = threadIdx.x;
    int m  = b * SEQLEN + c * LC + t;

    size_t o = (size_t)m * DINPROJ + DINNER + CONVDIM + h;
    float x   = g_zx[o] + g_zx[o + ZXPLANE] + dt_bias[h];
    float dtv = (x > 20.f) ? x : log1pf(expf(x));
    float a   = -expf(A_log[h]) * dtv;

    float sc = a;
#pragma unroll
    for (int o2 = 1; o2 < 32; o2 <<= 1) {
        float v = __shfl_up_sync(0xffffffffu, sc, o2);
        if ((t & 31) >= o2) sc += v;
    }
    __shared__ float w0tot;
    if (t == 31) w0tot = sc;
    __syncthreads();
    if (t >= 32) sc += w0tot;

    int idx = bh * SEQLEN + c * LC + t;
    g_dtv[idx] = dtv;
    g_cum[idx] = sc;
}

// ---------------- intra-chunk kernel (tensor cores, conflict-fixed) --------
#define OFF_SCUM 0
#define OFF_SDT  256
#define OFF_SW   512
#define PLANE128 (64*136*2)     // 17408
#define PLANE64  (64*72*2)      // 9216
#define PLANE128T (128*72*2)    // 18432
#define OFF_XTHI 768
#define OFF_XTLO (OFF_XTHI + PLANE64)
#define OFF_BIG  (OFF_XTLO + PLANE64)        // 19200
#define OFF_CHI  (OFF_BIG)
#define OFF_CLO  (OFF_CHI + PLANE128)
#define OFF_BHI  (OFF_CLO + PLANE128)
#define OFF_BLO  (OFF_BHI + PLANE128)
#define OFF_GHI  (OFF_BIG)
#define OFF_GLO  (OFF_GHI + PLANE64)
#define OFF_BWHI (OFF_GLO + PLANE64)
#define OFF_BWLO (OFF_BWHI + PLANE128T)
#define INTRA_SMEM (OFF_BIG + 4*PLANE128)    // 88832
__global__ __launch_bounds__(256, 2)
void intra_tc(const float* __restrict__ D_param) {
    extern __shared__ char smc[];
    uint32_t sb = smem_u32(smc);
    float* scum = (float*)(smc + OFF_SCUM);
    float* sdt  = (float*)(smc + OFF_SDT);
    float* sw   = (float*)(smc + OFF_SW);
    __nv_bfloat16* Xthi = (__nv_bfloat16*)(smc + OFF_XTHI);
    __nv_bfloat16* Xtlo = (__nv_bfloat16*)(smc + OFF_XTLO);
    __nv_bfloat16* Bwhi = (__nv_bfloat16*)(smc + OFF_BWHI);
    __nv_bfloat16* Bwlo = (__nv_bfloat16*)(smc + OFF_BWLO);
    __nv_bfloat16* Ghi  = (__nv_bfloat16*)(smc + OFF_GHI);
    __nv_bfloat16* Glo  = (__nv_bfloat16*)(smc + OFF_GLO);

    int g  = blockIdx.x;
    int c  = g & (NCHUNK - 1);
    int bh = g >> 3;
    int h  = bh % NHEADS;
    int b  = bh / NHEADS;
    int tid = threadIdx.x;
    int lane = tid & 31, wid = tid >> 5;
    int m0 = b * SEQLEN + c * LC;

    if (tid < 64) {
        scum[tid] = g_cum[bh * SEQLEN + c * LC + tid];
        sdt[tid]  = g_dtv[bh * SEQLEN + c * LC + tid];
    }
    for (int i = tid; i < 64 * 64; i += 256) {
        int r = i >> 6, q = (i & 63) * 2;
        float2 vc = *(const float2*)(g_Cm + (size_t)(m0 + r) * DSTATE + q);
        float2 vb = *(const float2*)(g_Bm + (size_t)(m0 + r) * DSTATE + q);
        uint32_t h2, l2;
        split2(vc, h2, l2);
        *(uint32_t*)(smc + OFF_CHI + (r * 136 + q) * 2) = h2;
        *(uint32_t*)(smc + OFF_CLO + (r * 136 + q) * 2) = l2;
        split2(vb, h2, l2);
        *(uint32_t*)(smc + OFF_BHI + (r * 136 + q) * 2) = h2;
        *(uint32_t*)(smc + OFF_BLO + (r * 136 + q) * 2) = l2;
    }
    // X transpose conversion — consecutive threads take consecutive t_
    // (stores hit consecutive 2B addresses => ~2-way conflicts max)
    for (int i = tid; i < 64 * 16; i += 256) {
        int t_ = i & 63, p4 = (i >> 6) * 4;
        float4 v = *(const float4*)(g_X + (size_t)(m0 + t_) * DINNER + h * HEADDIM + p4);
        float vv[4] = {v.x, v.y, v.z, v.w};
#pragma unroll
        for (int e = 0; e < 4; e++) {
            __nv_bfloat16 hh, ll;
            split1(vv[e], hh, ll);
            Xthi[(p4 + e) * 72 + t_] = hh;
            Xtlo[(p4 + e) * 72 + t_] = ll;
        }
    }
    __syncthreads();
    if (tid < 64) sw[tid] = expf(scum[63] - scum[tid]) * sdt[tid];
    __syncthreads();

    int wm = wid & 3, wn = wid >> 2;
    int brow8 = ((lane >> 4) & 1) * 8 + (lane & 7);
    int bcolb = ((lane >> 3) & 1) * 8;

    // ---- stage 1: G0 = C . B^T ----
    float acc1[4][4] = {};
    {
        for (int kk = 0; kk < 8; kk++) {
            uint32_t ah[4], al[4], bh2[4][2], bl2[4][2];
            int arow = wm * 16 + (lane & 15);
            int acol = (lane >> 4) * 8 + kk * 16;
            ldsm_x4(ah, sb + OFF_CHI + (arow * 136 + acol) * 2);
            ldsm_x4(al, sb + OFF_CLO + (arow * 136 + acol) * 2);
            int bcol = bcolb + kk * 16;
#pragma unroll
            for (int j2 = 0; j2 < 2; j2++) {
                int br = wn * 32 + j2 * 16 + brow8;
                ldsm_x4(&bh2[2 * j2][0], sb + OFF_BHI + (br * 136 + bcol) * 2);
                ldsm_x4(&bl2[2 * j2][0], sb + OFF_BLO + (br * 136 + bcol) * 2);
            }
#pragma unroll
            for (int j = 0; j < 4; j++) {
                mma_bf16(acc1[j], ah, bh2[j]);
                mma_bf16(acc1[j], ah, bl2[j]);
                mma_bf16(acc1[j], al, bh2[j]);
            }
        }
    }
    __syncthreads();   // C/B planes dead; reuse for G and Bwt

    {
        int tr = wm * 16 + (lane >> 2);
#pragma unroll
        for (int j = 0; j < 4; j++) {
            int sc0 = wn * 32 + j * 8 + (lane & 3) * 2;
#pragma unroll
            for (int hlf = 0; hlf < 2; hlf++) {
                int t_ = tr + hlf * 8;
#pragma unroll
                for (int e = 0; e < 2; e++) {
                    int s_ = sc0 + e;
                    float wgt = (s_ <= t_) ? expf(scum[t_] - scum[s_]) * sdt[s_] : 0.f;
                    float gv = acc1[j][hlf * 2 + e] * wgt;
                    __nv_bfloat16 hh, ll;
                    split1(gv, hh, ll);
                    Ghi[t_ * 72 + s_] = hh;
                    Glo[t_ * 72 + s_] = ll;
                }
            }
        }
    }
    // Bwt[n][s] = w[s]*B[s][n] — consecutive threads take consecutive s_
    for (int i = tid; i < 64 * 32; i += 256) {
        int s_ = i & 63, n4 = (i >> 6) * 4;
        float4 v = *(const float4*)(g_Bm + (size_t)(m0 + s_) * DSTATE + n4);
        float w = sw[s_];
        float vv[4] = {v.x * w, v.y * w, v.z * w, v.w * w};
#pragma unroll
        for (int e = 0; e < 4; e++) {
            __nv_bfloat16 hh, ll;
            split1(vv[e], hh, ll);
            Bwhi[(n4 + e) * 72 + s_] = hh;
            Bwlo[(n4 + e) * 72 + s_] = ll;
        }
    }
    __syncthreads();

    // ---- stage 2: Y = G . Xt^T (+ D*x) ----
    {
        float acc[4][4] = {};
        for (int kk = 0; kk < 4; kk++) {
            uint32_t ah[4], al[4], bh2[4][2], bl2[4][2];
            int arow = wm * 16 + (lane & 15);
            int acol = (lane >> 4) * 8 + kk * 16;
            ldsm_x4(ah, sb + OFF_GHI + (arow * 72 + acol) * 2);
            ldsm_x4(al, sb + OFF_GLO + (arow * 72 + acol) * 2);
            int bcol = bcolb + kk * 16;
#pragma unroll
            for (int j2 = 0; j2 < 2; j2++) {
                int br = wn * 32 + j2 * 16 + brow8;
                ldsm_x4(&bh2[2 * j2][0], sb + OFF_XTHI + (br * 72 + bcol) * 2);
                ldsm_x4(&bl2[2 * j2][0], sb + OFF_XTLO + (br * 72 + bcol) * 2);
            }
#pragma unroll
            for (int j = 0; j < 4; j++) {
                mma_bf16(acc[j], ah, bh2[j]);
                mma_bf16(acc[j], ah, bl2[j]);
                mma_bf16(acc[j], al, bh2[j]);
            }
        }
        float Dp = D_param[h];
        int tr = wm * 16 + (lane >> 2);
#pragma unroll
        for (int j = 0; j < 4; j++) {
            int p0 = wn * 32 + j * 8 + (lane & 3) * 2;
#pragma unroll
            for (int hlf = 0; hlf < 2; hlf++) {
                int t_ = tr + hlf * 8;
#pragma unroll
                for (int e = 0; e < 2; e++) {
                    int p_ = p0 + e;
                    float xv = __bfloat162float(Xthi[p_ * 72 + t_])
                             + __bfloat162float(Xtlo[p_ * 72 + t_]);
                    g_Y0[(size_t)(m0 + t_) * DINNER + h * HEADDIM + p_] =
                        acc[j][hlf * 2 + e] + Dp * xv;
                }
            }
        }
    }

    // ---- stage 3: S = Xt . Bwt^T ----
    {
        float acc[8][4] = {};
        for (int kk = 0; kk < 4; kk++) {
            uint32_t ah[4], al[4], bh2[8][2], bl2[8][2];
            int arow = wm * 16 + (lane & 15);
            int acol = (lane >> 4) * 8 + kk * 16;
            ldsm_x4(ah, sb + OFF_XTHI + (arow * 72 + acol) * 2);
            ldsm_x4(al, sb + OFF_XTLO + (arow * 72 + acol) * 2);
            int bcol = bcolb + kk * 16;
#pragma unroll
            for (int j2 = 0; j2 < 4; j2++) {
                int br = wn * 64 + j2 * 16 + brow8;
                ldsm_x4(&bh2[2 * j2][0], sb + OFF_BWHI + (br * 72 + bcol) * 2);
                ldsm_x4(&bl2[2 * j2][0], sb + OFF_BWLO + (br * 72 + bcol) * 2);
            }
#pragma unroll
            for (int j = 0; j < 8; j++) {
                mma_bf16(acc[j], ah, bh2[j]);
                mma_bf16(acc[j], ah, bl2[j]);
                mma_bf16(acc[j], al, bh2[j]);
            }
        }
        size_t base = (size_t)(bh * NCHUNK + c) * (HEADDIM * DSTATE);
        int pr = wm * 16 + (lane >> 2);
#pragma unroll
        for (int j = 0; j < 8; j++) {
            int n0_ = wn * 64 + j * 8 + (lane & 3) * 2;
#pragma unroll
            for (int hlf = 0; hlf < 2; hlf++) {
                int p_ = pr + hlf * 8;
#pragma unroll
                for (int e = 0; e < 2; e++) {
                    g_S[base + p_ * DSTATE + n0_ + e] = acc[j][hlf * 2 + e];
                }
            }
        }
    }
}

// ---------------- inter-chunk state scan: 192 blocks, 1 float4/thread -------
__global__ void chunkscan_kernel() {
    int bh   = blockIdx.x >> 2;
    int part = blockIdx.x & 3;
    int idx4 = part * 2048 + threadIdx.x * 4;
    float4 E = make_float4(0.f, 0.f, 0.f, 0.f);
    size_t base = (size_t)bh * NCHUNK * (HEADDIM * DSTATE);
#pragma unroll
    for (int k = 0; k < NCHUNK; k++) {
        float dAk = expf(g_cum[bh * SEQLEN + k * LC + (LC - 1)]);
        size_t off = base + (size_t)k * (HEADDIM * DSTATE) + idx4;
        *(float4*)(g_P + off) = E;
        float4 s = *(const float4*)(g_S + off);
        E.x = s.x + dAk * E.x;
        E.y = s.y + dAk * E.y;
        E.z = s.z + dAk * E.z;
        E.w = s.w + dAk * E.w;
    }
}

// ---------------- inter-chunk Y + gating + bf16 split -----------------------
#define SB_STRIDE 132
#define SMEMD_FLOATS (2*64*SB_STRIDE + 64)
__global__ __launch_bounds__(256)
void inter_gate_kernel() {
    extern __shared__ float sm[];
    float* sC   = sm;
    float* sP   = sC + 64 * SB_STRIDE;
    float* scum = sP + 64 * SB_STRIDE;

    int g  = blockIdx.x;
    int c  = g & (NCHUNK - 1);
    int bh = g >> 3;
    int h  = bh % NHEADS;
    int b  = bh / NHEADS;
    int tid = threadIdx.x;
    int m0 = b * SEQLEN + c * LC;
    size_t pbase = (size_t)(bh * NCHUNK + c) * (HEADDIM * DSTATE);

    for (int i = tid; i < 64 * 32; i += 256) {
        int r = i >> 5, q = i & 31;
        *(float4*)(sC + r * SB_STRIDE + q * 4) =
            *(const float4*)(g_Cm + (size_t)(m0 + r) * DSTATE + q * 4);
        *(float4*)(sP + r * SB_STRIDE + q * 4) =
            *(const float4*)(g_P + pbase + r * DSTATE + q * 4);
    }
    if (tid < 64) scum[tid] = g_cum[bh * SEQLEN + c * LC + tid];
    __syncthreads();

    int tx = tid & 15, ty = tid >> 4;
    int rot = (tid & 15) * 4;
    float acc[4][4] = {};
    for (int n0_ = 0; n0_ < 128; n0_ += 4) {
        int n = (n0_ + rot) & 127;
        float4 a4[4], b4[4];
#pragma unroll
        for (int i = 0; i < 4; i++) a4[i] = *(float4*)(sC + (ty * 4 + i) * SB_STRIDE + n);
#pragma unroll
        for (int j = 0; j < 4; j++) b4[j] = *(float4*)(sP + (tx * 4 + j) * SB_STRIDE + n);
#pragma unroll
        for (int i = 0; i < 4; i++)
#pragma unroll
            for (int j = 0; j < 4; j++)
                acc[i][j] += a4[i].x * b4[j].x + a4[i].y * b4[j].y
                           + a4[i].z * b4[j].z + a4[i].w * b4[j].w;
    }
#pragma unroll
    for (int i = 0; i < 4; i++) {
        int t_ = ty * 4 + i;
        float dec = expf(scum[t_]);
#pragma unroll
        for (int j = 0; j < 4; j++) {
            int p_ = tx * 4 + j;
            size_t mi = (size_t)(m0 + t_) * DINNER + h * HEADDIM + p_;
            float y = g_Y0[mi] + dec * acc[i][j];
            size_t zo = (size_t)(m0 + t_) * DINPROJ + h * HEADDIM + p_;
            float z = g_zx[zo] + g_zx[zo + ZXPLANE];
            float gv = y * (z / (1.f + expf(-z)));
            __nv_bfloat16 hb, lb;
            split1(gv, hb, lb);
            g_ghi[mi] = hb;
            g_glo[mi] = lb;
        }
    }
}

// ---------------- launch ----------------------------------------------------
extern "C" void kernel_launch(void* const* d_in, const int* in_sizes, int n_in,
                              void* d_out, int out_size) {
    const float* u       = (const float*)d_in[0];
    const float* W_in    = (const float*)d_in[1];
    const float* conv_w  = (const float*)d_in[2];
    const float* conv_b  = (const float*)d_in[3];
    const float* dt_bias = (const float*)d_in[4];
    const float* A_log   = (const float*)d_in[5];
    const float* D_param = (const float*)d_in[6];
    const float* W_out   = (const float*)d_in[7];
    float* out = (float*)d_out;

    float *zx, *pp;
    cudaGetSymbolAddress((void**)&zx, g_zx);
    cudaGetSymbolAddress((void**)&pp, g_pp);
    __nv_bfloat16 *uhi, *ulo, *wih, *wil, *ghi, *glo, *woh, *wol;
    cudaGetSymbolAddress((void**)&uhi, g_uhi);  cudaGetSymbolAddress((void**)&ulo, g_ulo);
    cudaGetSymbolAddress((void**)&wih, g_wih);  cudaGetSymbolAddress((void**)&wil, g_wil);
    cudaGetSymbolAddress((void**)&ghi, g_ghi);  cudaGetSymbolAddress((void**)&glo, g_glo);
    cudaGetSymbolAddress((void**)&woh, g_woh);  cudaGetSymbolAddress((void**)&wol, g_wol);

    static bool attr_done = false;
    if (!attr_done) {
        cudaFuncSetAttribute(intra_tc, cudaFuncAttributeMaxDynamicSharedMemorySize,
                             INTRA_SMEM);
        cudaFuncSetAttribute(inter_gate_kernel, cudaFuncAttributeMaxDynamicSharedMemorySize,
                             SMEMD_FLOATS * sizeof(float));
        cudaFuncSetAttribute(mma_gemm, cudaFuncAttributeMaxDynamicSharedMemorySize,
                             GNSTAGE * GSTAGE_BYTES);
        attr_done = true;
    }
    const int TC_SMEM = GNSTAGE * GSTAGE_BYTES;  // 98304

    // 0. fused vectorized split of u, W_in, W_out
    {
        int ntot4 = (N_U + N_WI + N_WO) / 4;
        split_all_kernel<<<(ntot4 + 255) / 256, 256>>>(u, W_in, W_out);
    }
    // 1. in-projection, split-K x2 (consumers fuse the reduction)
    {
        dim3 grid(NPAD_IN / 128, MROWS / 128, INSPLIT);
        mma_gemm<<<grid, 256, TC_SMEM>>>(uhi, ulo, wih, wil, zx,
                                         DMODEL, DINPROJ, DINPROJ, (size_t)ZXPLANE);
    }
    // 2. causal conv + silu (sums 2 zx planes)
    conv_kernel<<<(MROWS * CONVDIM + 255) / 256, 256>>>(conv_w, conv_b);
    // 3. dt + within-chunk cumsum (sums 2 zx planes)
    dtcum_kernel<<<NBH * NCHUNK, 64>>>(dt_bias, A_log);
    // 4. intra-chunk (tensor cores)
    intra_tc<<<NBH * NCHUNK, 256, INTRA_SMEM>>>(D_param);
    // 5. inter-chunk state scan
    chunkscan_kernel<<<NBH * 4, 512>>>();
    // 6. inter-chunk Y + gating (sums 2 zx planes)
    inter_gate_kernel<<<NBH * NCHUNK, 256, SMEMD_FLOATS * sizeof(float)>>>();
    // 7. out-projection, split-K x6, then reduce
    {
        dim3 grid(DMODEL / 128, MROWS / 128, NSPLIT);
        mma_gemm<<<grid, 256, TC_SMEM>>>(ghi, glo, woh, wol, pp,
                                         DINNER, DMODEL, DMODEL,
                                         (size_t)MROWS * DMODEL);
        reduce_kernel<<<(MROWS * DMODEL / 4 + 255) / 256, 256>>>(out);
    }
}

// round 16
// speedup vs baseline: 1.1229x; 1.0217x over previous
#include <cuda_runtime.h>
#include <cuda_bf16.h>
#include <math.h>
#include <cstdint>

#define BATCH   2
#define SEQLEN  512
#define DMODEL  768
#define DINNER  1536
#define NHEADS  24
#define HEADDIM 64
#define DSTATE  128
#define CONVDIM 1792
#define DINPROJ 3352
#define MROWS   (BATCH*SEQLEN)  // 1024
#define LC      64
#define NCHUNK  (SEQLEN/LC)     // 8
#define NBH     (BATCH*NHEADS)  // 48
#define NPAD_IN 3456
#define NSPLIT  6
#define ZXPLANE (MROWS * DINPROJ)
#define INSPLIT 2

// ---------------- scratch ---------------------------------------------------
__device__ float g_zx [INSPLIT * ZXPLANE];
__device__ float g_X  [MROWS * DINNER];
__device__ float g_Bm [MROWS * DSTATE];
__device__ float g_Cm [MROWS * DSTATE];
__device__ float g_dtv[NBH * SEQLEN];
__device__ float g_cum[NBH * SEQLEN];
__device__ float g_Y0 [MROWS * DINNER];
__device__ float g_S  [NBH * NCHUNK * HEADDIM * DSTATE];
__device__ float g_P  [NBH * NCHUNK * HEADDIM * DSTATE];
__device__ float g_pp [NSPLIT * MROWS * DMODEL];

__device__ __align__(256) __nv_bfloat16 g_uhi[MROWS * DMODEL],   g_ulo[MROWS * DMODEL];
__device__ __align__(256) __nv_bfloat16 g_wih[NPAD_IN * DMODEL], g_wil[NPAD_IN * DMODEL];
__device__ __align__(256) __nv_bfloat16 g_ghi[MROWS * DINNER],   g_glo[MROWS * DINNER];
__device__ __align__(256) __nv_bfloat16 g_woh[DMODEL * DINNER],  g_wol[DMODEL * DINNER];

// ================= helpers =================================================
__device__ __forceinline__ uint32_t smem_u32(const void* p) {
    uint32_t a;
    asm("{ .reg .u64 t; cvta.to.shared.u64 t, %1; cvt.u32.u64 %0, t; }"
        : "=r"(a) : "l"(p));
    return a;
}
__device__ __forceinline__ void ldsm_x4(uint32_t* r, uint32_t addr) {
    asm volatile("ldmatrix.sync.aligned.m8n8.x4.shared.b16 {%0,%1,%2,%3}, [%4];"
                 : "=r"(r[0]), "=r"(r[1]), "=r"(r[2]), "=r"(r[3]) : "r"(addr));
}
__device__ __forceinline__ void ldsm_x2(uint32_t* r, uint32_t addr) {
    asm volatile("ldmatrix.sync.aligned.m8n8.x2.shared.b16 {%0,%1}, [%2];"
                 : "=r"(r[0]), "=r"(r[1]) : "r"(addr));
}
__device__ __forceinline__ void mma_bf16(float* c, const uint32_t* a, const uint32_t* b) {
    asm volatile(
        "mma.sync.aligned.m16n8k16.row.col.f32.bf16.bf16.f32 "
        "{%0,%1,%2,%3}, {%4,%5,%6,%7}, {%8,%9}, {%0,%1,%2,%3};"
        : "+f"(c[0]), "+f"(c[1]), "+f"(c[2]), "+f"(c[3])
        : "r"(a[0]), "r"(a[1]), "r"(a[2]), "r"(a[3]), "r"(b[0]), "r"(b[1]));
}
__device__ __forceinline__ void split1(float v, __nv_bfloat16& h, __nv_bfloat16& l) {
    h = __float2bfloat16(v);
    l = __float2bfloat16(v - __bfloat162float(h));
}
__device__ __forceinline__ void split2(float2 v, uint32_t& hi2, uint32_t& lo2) {
    __nv_bfloat16 h0, l0, h1, l1;
    split1(v.x, h0, l0);
    split1(v.y, h1, l1);
    __nv_bfloat162 H, L;
    H.x = h0; H.y = h1; L.x = l0; L.y = l1;
    hi2 = *(uint32_t*)&H;
    lo2 = *(uint32_t*)&L;
}
__device__ __forceinline__ void split4_store(float4 v, __nv_bfloat16* hi, __nv_bfloat16* lo, int j) {
    uint32_t h01, l01, h23, l23;
    split2(make_float2(v.x, v.y), h01, l01);
    split2(make_float2(v.z, v.w), h23, l23);
    uint2 H = make_uint2(h01, h23), L = make_uint2(l01, l23);
    *(uint2*)(hi + j) = H;
    *(uint2*)(lo + j) = L;
}

// ================= fused vectorized split of u, W_in(+pad), W_out ==========
#define N_U  (MROWS * DMODEL)
#define N_WI (NPAD_IN * DMODEL)
#define N_WIS (DINPROJ * DMODEL)
#define N_WO (DMODEL * DINNER)
__global__ void split_all_kernel(const float* __restrict__ u,
                                 const float* __restrict__ W_in,
                                 const float* __restrict__ W_out) {
    int i4 = blockIdx.x * blockDim.x + threadIdx.x;
    int i = i4 * 4;
    if (i < N_U) {
        float4 v = *(const float4*)(u + i);
        split4_store(v, g_uhi, g_ulo, i);
    } else if (i < N_U + N_WI) {
        int j = i - N_U;
        float4 v = (j < N_WIS) ? *(const float4*)(W_in + j)
                               : make_float4(0.f, 0.f, 0.f, 0.f);
        split4_store(v, g_wih, g_wil, j);
    } else if (i < N_U + N_WI + N_WO) {
        int j = i - N_U - N_WI;
        float4 v = *(const float4*)(W_out + j);
        split4_store(v, g_woh, g_wol, j);
    }
}

// ================= mma.sync bf16 GEMM, 4-stage pipeline ====================
#define GSTRIDE 24
#define GOP_BYTES (128 * GSTRIDE * 2)      // 6144
#define GSTAGE_BYTES (4 * GOP_BYTES)       // 24576
#define GNSTAGE 4
__global__ __launch_bounds__(256, 2)
void mma_gemm(const __nv_bfloat16* __restrict__ Ahi, const __nv_bfloat16* __restrict__ Alo,
              const __nv_bfloat16* __restrict__ Bhi, const __nv_bfloat16* __restrict__ Blo,
              float* __restrict__ C, int Ktot, int Nact, int ldc, size_t csplit) {
    extern __shared__ char smx[];
    uint32_t sb = smem_u32(smx);
    int tid  = threadIdx.x;
    int lane = tid & 31, wid = tid >> 5;
    int wm = wid >> 2, wn = wid & 3;
    int m0 = blockIdx.y * 128, n0 = blockIdx.x * 128;
    int nsp  = gridDim.z;
    int Klen = Ktot / nsp;
    int k0   = blockIdx.z * Klen;
    float* Cp = C + (size_t)blockIdx.z * csplit;
    const int KT = Klen / 16;

    const __nv_bfloat16* ptrs[4] = {Ahi, Alo, Bhi, Blo};
    int rbase[4] = {m0, m0, n0, n0};

    auto load_stage = [&](int kt, int s) {
        uint32_t sbase = sb + s * GSTAGE_BYTES;
#pragma unroll
        for (int op = 0; op < 4; op++) {
            int r = tid >> 1, hf = tid & 1;
            const void* g = ptrs[op] + (size_t)(rbase[op] + r) * Ktot + k0 + kt * 16 + hf * 8;
            uint32_t d = sbase + op * GOP_BYTES + (r * GSTRIDE + hf * 8) * 2;
            asm volatile("cp.async.cg.shared.global [%0], [%1], 16;" :: "r"(d), "l"(g));
        }
        asm volatile("cp.async.commit_group;");
    };

    float acc[4][4][4];
#pragma unroll
    for (int i = 0; i < 4; i++)
#pragma unroll
        for (int j = 0; j < 4; j++)
#pragma unroll
            for (int q = 0; q < 4; q++) acc[i][j][q] = 0.f;

    load_stage(0, 0);
    load_stage(1, 1);
    load_stage(2, 2);

    for (int kt = 0; kt < KT; kt++) {
        asm volatile("cp.async.wait_group 2;");
        __syncthreads();

        uint32_t st = sb + (kt & 3) * GSTAGE_BYTES;
        uint32_t ah[4][4], al[4][4], bh[4][2], bl[4][2];
        int arow = wm * 64 + (lane & 15);
        int acol = (lane >> 4) * 8;
#pragma unroll
        for (int i = 0; i < 4; i++) {
            uint32_t off = ((arow + i * 16) * GSTRIDE + acol) * 2;
            ldsm_x4(ah[i], st + off);
            ldsm_x4(al[i], st + GOP_BYTES + off);
        }
        int brow = wn * 32 + (lane & 7);
        int bcol = ((lane >> 3) & 1) * 8;
#pragma unroll
        for (int j = 0; j < 4; j++) {
            uint32_t off = ((brow + j * 8) * GSTRIDE + bcol) * 2;
            ldsm_x2(bh[j], st + 2 * GOP_BYTES + off);
            ldsm_x2(bl[j], st + 3 * GOP_BYTES + off);
        }
#pragma unroll
        for (int i = 0; i < 4; i++)
#pragma unroll
            for (int j = 0; j < 4; j++) {
                mma_bf16(acc[i][j], ah[i], bh[j]);
                mma_bf16(acc[i][j], ah[i], bl[j]);
                mma_bf16(acc[i][j], al[i], bh[j]);
            }

        if (kt + 3 < KT) load_stage(kt + 3, (kt + 3) & 3);
        else             asm volatile("cp.async.commit_group;");
    }

    int r0 = m0 + wm * 64 + (lane >> 2);
    int c0 = n0 + wn * 32 + (lane & 3) * 2;
#pragma unroll
    for (int i = 0; i < 4; i++) {
#pragma unroll
        for (int j = 0; j < 4; j++) {
            int rr = r0 + i * 16;
            int cc = c0 + j * 8;
            if (cc < Nact)     Cp[(size_t)rr * ldc + cc]           = acc[i][j][0];
            if (cc + 1 < Nact) Cp[(size_t)rr * ldc + cc + 1]       = acc[i][j][1];
            if (cc < Nact)     Cp[(size_t)(rr + 8) * ldc + cc]     = acc[i][j][2];
            if (cc + 1 < Nact) Cp[(size_t)(rr + 8) * ldc + cc + 1] = acc[i][j][3];
        }
    }
}

// ---------------- reduce NSPLIT partials -> out -----------------------------
__global__ void reduce_kernel(float* __restrict__ out) {
    int i = blockIdx.x * blockDim.x + threadIdx.x;
    const int n4 = MROWS * DMODEL / 4;
    if (i >= n4) return;
    float4 r = make_float4(0.f, 0.f, 0.f, 0.f);
#pragma unroll
    for (int s = 0; s < NSPLIT; s++) {
        float4 a = *(const float4*)(g_pp + (size_t)s * MROWS * DMODEL + i * 4);
        r.x += a.x; r.y += a.y; r.z += a.z; r.w += a.w;
    }
    *(float4*)(out + i * 4) = r;
}

// ---------------- fused: scalar conv+SiLU (R15 code)  AND  dt/cumsum --------
#define CONV_BLOCKS ((MROWS * CONVDIM + 255) / 256)   // 7168
#define DT_BLOCKS (NBH * NCHUNK / 4)                  // 96
__global__ void conv_dt_kernel(const float* __restrict__ conv_w,
                               const float* __restrict__ conv_b,
                               const float* __restrict__ dt_bias,
                               const float* __restrict__ A_log) {
    if (blockIdx.x < CONV_BLOCKS) {
        int idx = blockIdx.x * 256 + threadIdx.x;
        if (idx >= MROWS * CONVDIM) return;
        int c = idx % CONVDIM;
        int m = idx / CONVDIM;
        int t = m % SEQLEN;
        float s = conv_b[c];
#pragma unroll
        for (int k = 0; k < 4; k++) {
            int tt = t - 3 + k;
            if (tt >= 0) {
                size_t o = (size_t)(m - 3 + k) * DINPROJ + DINNER + c;
                s += (g_zx[o] + g_zx[o + ZXPLANE]) * conv_w[c * 4 + k];
            }
        }
        float v = s / (1.f + expf(-s));
        if (c < DINNER)                g_X [m * DINNER + c] = v;
        else if (c < DINNER + DSTATE)  g_Bm[m * DSTATE + (c - DINNER)] = v;
        else                           g_Cm[m * DSTATE + (c - DINNER - DSTATE)] = v;
    } else {
        // dtcum: 4 chunks of 64 per 256-thread block
        __shared__ float w0tot[4];
        int sub = threadIdx.x >> 6;
        int t   = threadIdx.x & 63;
        int g   = (blockIdx.x - CONV_BLOCKS) * 4 + sub;
        int c   = g & (NCHUNK - 1);
        int bh  = g >> 3;
        int h   = bh % NHEADS;
        int b   = bh / NHEADS;
        int m   = b * SEQLEN + c * LC + t;

        size_t o = (size_t)m * DINPROJ + DINNER + CONVDIM + h;
        float x   = g_zx[o] + g_zx[o + ZXPLANE] + dt_bias[h];
        float dtv = (x > 20.f) ? x : log1pf(expf(x));
        float a   = -expf(A_log[h]) * dtv;

        float sc = a;
#pragma unroll
        for (int o2 = 1; o2 < 32; o2 <<= 1) {
            float v = __shfl_up_sync(0xffffffffu, sc, o2);
            if ((t & 31) >= o2) sc += v;
        }
        if (t == 31) w0tot[sub] = sc;
        __syncthreads();
        if (t >= 32) sc += w0tot[sub];

        int idx = bh * SEQLEN + c * LC + t;
        g_dtv[idx] = dtv;
        g_cum[idx] = sc;
    }
}

// ---------------- intra-chunk kernel (tensor cores, conflict-fixed) --------
#define OFF_SCUM 0
#define OFF_SDT  256
#define OFF_SW   512
#define PLANE128 (64*136*2)     // 17408
#define PLANE64  (64*72*2)      // 9216
#define PLANE128T (128*72*2)    // 18432
#define OFF_XTHI 768
#define OFF_XTLO (OFF_XTHI + PLANE64)
#define OFF_BIG  (OFF_XTLO + PLANE64)        // 19200
#define OFF_CHI  (OFF_BIG)
#define OFF_CLO  (OFF_CHI + PLANE128)
#define OFF_BHI  (OFF_CLO + PLANE128)
#define OFF_BLO  (OFF_BHI + PLANE128)
#define OFF_GHI  (OFF_BIG)
#define OFF_GLO  (OFF_GHI + PLANE64)
#define OFF_BWHI (OFF_GLO + PLANE64)
#define OFF_BWLO (OFF_BWHI + PLANE128T)
#define INTRA_SMEM (OFF_BIG + 4*PLANE128)    // 88832
__global__ __launch_bounds__(256, 2)
void intra_tc(const float* __restrict__ D_param) {
    extern __shared__ char smc[];
    uint32_t sb = smem_u32(smc);
    float* scum = (float*)(smc + OFF_SCUM);
    float* sdt  = (float*)(smc + OFF_SDT);
    float* sw   = (float*)(smc + OFF_SW);
    __nv_bfloat16* Xthi = (__nv_bfloat16*)(smc + OFF_XTHI);
    __nv_bfloat16* Xtlo = (__nv_bfloat16*)(smc + OFF_XTLO);
    __nv_bfloat16* Bwhi = (__nv_bfloat16*)(smc + OFF_BWHI);
    __nv_bfloat16* Bwlo = (__nv_bfloat16*)(smc + OFF_BWLO);
    __nv_bfloat16* Ghi  = (__nv_bfloat16*)(smc + OFF_GHI);
    __nv_bfloat16* Glo  = (__nv_bfloat16*)(smc + OFF_GLO);

    int g  = blockIdx.x;
    int c  = g & (NCHUNK - 1);
    int bh = g >> 3;
    int h  = bh % NHEADS;
    int b  = bh / NHEADS;
    int tid = threadIdx.x;
    int lane = tid & 31, wid = tid >> 5;
    int m0 = b * SEQLEN + c * LC;

    if (tid < 64) {
        scum[tid] = g_cum[bh * SEQLEN + c * LC + tid];
        sdt[tid]  = g_dtv[bh * SEQLEN + c * LC + tid];
    }
    for (int i = tid; i < 64 * 64; i += 256) {
        int r = i >> 6, q = (i & 63) * 2;
        float2 vc = *(const float2*)(g_Cm + (size_t)(m0 + r) * DSTATE + q);
        float2 vb = *(const float2*)(g_Bm + (size_t)(m0 + r) * DSTATE + q);
        uint32_t h2, l2;
        split2(vc, h2, l2);
        *(uint32_t*)(smc + OFF_CHI + (r * 136 + q) * 2) = h2;
        *(uint32_t*)(smc + OFF_CLO + (r * 136 + q) * 2) = l2;
        split2(vb, h2, l2);
        *(uint32_t*)(smc + OFF_BHI + (r * 136 + q) * 2) = h2;
        *(uint32_t*)(smc + OFF_BLO + (r * 136 + q) * 2) = l2;
    }
    // X transpose conversion — consecutive threads take consecutive t_
    for (int i = tid; i < 64 * 16; i += 256) {
        int t_ = i & 63, p4 = (i >> 6) * 4;
        float4 v = *(const float4*)(g_X + (size_t)(m0 + t_) * DINNER + h * HEADDIM + p4);
        float vv[4] = {v.x, v.y, v.z, v.w};
#pragma unroll
        for (int e = 0; e < 4; e++) {
            __nv_bfloat16 hh, ll;
            split1(vv[e], hh, ll);
            Xthi[(p4 + e) * 72 + t_] = hh;
            Xtlo[(p4 + e) * 72 + t_] = ll;
        }
    }
    __syncthreads();
    if (tid < 64) sw[tid] = expf(scum[63] - scum[tid]) * sdt[tid];
    __syncthreads();

    int wm = wid & 3, wn = wid >> 2;
    int brow8 = ((lane >> 4) & 1) * 8 + (lane & 7);
    int bcolb = ((lane >> 3) & 1) * 8;

    // ---- stage 1: G0 = C . B^T ----
    float acc1[4][4] = {};
    {
        for (int kk = 0; kk < 8; kk++) {
            uint32_t ah[4], al[4], bh2[4][2], bl2[4][2];
            int arow = wm * 16 + (lane & 15);
            int acol = (lane >> 4) * 8 + kk * 16;
            ldsm_x4(ah, sb + OFF_CHI + (arow * 136 + acol) * 2);
            ldsm_x4(al, sb + OFF_CLO + (arow * 136 + acol) * 2);
            int bcol = bcolb + kk * 16;
#pragma unroll
            for (int j2 = 0; j2 < 2; j2++) {
                int br = wn * 32 + j2 * 16 + brow8;
                ldsm_x4(&bh2[2 * j2][0], sb + OFF_BHI + (br * 136 + bcol) * 2);
                ldsm_x4(&bl2[2 * j2][0], sb + OFF_BLO + (br * 136 + bcol) * 2);
            }
#pragma unroll
            for (int j = 0; j < 4; j++) {
                mma_bf16(acc1[j], ah, bh2[j]);
                mma_bf16(acc1[j], ah, bl2[j]);
                mma_bf16(acc1[j], al, bh2[j]);
            }
        }
    }
    __syncthreads();   // C/B planes dead; reuse for G and Bwt

    {
        int tr = wm * 16 + (lane >> 2);
#pragma unroll
        for (int j = 0; j < 4; j++) {
            int sc0 = wn * 32 + j * 8 + (lane & 3) * 2;
#pragma unroll
            for (int hlf = 0; hlf < 2; hlf++) {
                int t_ = tr + hlf * 8;
#pragma unroll
                for (int e = 0; e < 2; e++) {
                    int s_ = sc0 + e;
                    float wgt = (s_ <= t_) ? expf(scum[t_] - scum[s_]) * sdt[s_] : 0.f;
                    float gv = acc1[j][hlf * 2 + e] * wgt;
                    __nv_bfloat16 hh, ll;
                    split1(gv, hh, ll);
                    Ghi[t_ * 72 + s_] = hh;
                    Glo[t_ * 72 + s_] = ll;
                }
            }
        }
    }
    // Bwt[n][s] = w[s]*B[s][n] — consecutive threads take consecutive s_
    for (int i = tid; i < 64 * 32; i += 256) {
        int s_ = i & 63, n4 = (i >> 6) * 4;
        float4 v = *(const float4*)(g_Bm + (size_t)(m0 + s_) * DSTATE + n4);
        float w = sw[s_];
        float vv[4] = {v.x * w, v.y * w, v.z * w, v.w * w};
#pragma unroll
        for (int e = 0; e < 4; e++) {
            __nv_bfloat16 hh, ll;
            split1(vv[e], hh, ll);
            Bwhi[(n4 + e) * 72 + s_] = hh;
            Bwlo[(n4 + e) * 72 + s_] = ll;
        }
    }
    __syncthreads();

    // ---- stage 2: Y = G . Xt^T (+ D*x) ----
    {
        float acc[4][4] = {};
        for (int kk = 0; kk < 4; kk++) {
            uint32_t ah[4], al[4], bh2[4][2], bl2[4][2];
            int arow = wm * 16 + (lane & 15);
            int acol = (lane >> 4) * 8 + kk * 16;
            ldsm_x4(ah, sb + OFF_GHI + (arow * 72 + acol) * 2);
            ldsm_x4(al, sb + OFF_GLO + (arow * 72 + acol) * 2);
            int bcol = bcolb + kk * 16;
#pragma unroll
            for (int j2 = 0; j2 < 2; j2++) {
                int br = wn * 32 + j2 * 16 + brow8;
                ldsm_x4(&bh2[2 * j2][0], sb + OFF_XTHI + (br * 72 + bcol) * 2);
                ldsm_x4(&bl2[2 * j2][0], sb + OFF_XTLO + (br * 72 + bcol) * 2);
            }
#pragma unroll
            for (int j = 0; j < 4; j++) {
                mma_bf16(acc[j], ah, bh2[j]);
                mma_bf16(acc[j], ah, bl2[j]);
                mma_bf16(acc[j], al, bh2[j]);
            }
        }
        float Dp = D_param[h];
        int tr = wm * 16 + (lane >> 2);
#pragma unroll
        for (int j = 0; j < 4; j++) {
            int p0 = wn * 32 + j * 8 + (lane & 3) * 2;
#pragma unroll
            for (int hlf = 0; hlf < 2; hlf++) {
                int t_ = tr + hlf * 8;
#pragma unroll
                for (int e = 0; e < 2; e++) {
                    int p_ = p0 + e;
                    float xv = __bfloat162float(Xthi[p_ * 72 + t_])
                             + __bfloat162float(Xtlo[p_ * 72 + t_]);
                    g_Y0[(size_t)(m0 + t_) * DINNER + h * HEADDIM + p_] =
                        acc[j][hlf * 2 + e] + Dp * xv;
                }
            }
        }
    }

    // ---- stage 3: S = Xt . Bwt^T ----
    {
        float acc[8][4] = {};
        for (int kk = 0; kk < 4; kk++) {
            uint32_t ah[4], al[4], bh2[8][2], bl2[8][2];
            int arow = wm * 16 + (lane & 15);
            int acol = (lane >> 4) * 8 + kk * 16;
            ldsm_x4(ah, sb + OFF_XTHI + (arow * 72 + acol) * 2);
            ldsm_x4(al, sb + OFF_XTLO + (arow * 72 + acol) * 2);
            int bcol = bcolb + kk * 16;
#pragma unroll
            for (int j2 = 0; j2 < 4; j2++) {
                int br = wn * 64 + j2 * 16 + brow8;
                ldsm_x4(&bh2[2 * j2][0], sb + OFF_BWHI + (br * 72 + bcol) * 2);
                ldsm_x4(&bl2[2 * j2][0], sb + OFF_BWLO + (br * 72 + bcol) * 2);
            }
#pragma unroll
            for (int j = 0; j < 8; j++) {
                mma_bf16(acc[j], ah, bh2[j]);
                mma_bf16(acc[j], ah, bl2[j]);
                mma_bf16(acc[j], al, bh2[j]);
            }
        }
        size_t base = (size_t)(bh * NCHUNK + c) * (HEADDIM * DSTATE);
        int pr = wm * 16 + (lane >> 2);
#pragma unroll
        for (int j = 0; j < 8; j++) {
            int n0_ = wn * 64 + j * 8 + (lane & 3) * 2;
#pragma unroll
            for (int hlf = 0; hlf < 2; hlf++) {
                int p_ = pr + hlf * 8;
#pragma unroll
                for (int e = 0; e < 2; e++) {
                    g_S[base + p_ * DSTATE + n0_ + e] = acc[j][hlf * 2 + e];
                }
            }
        }
    }
}

// ---------------- inter-chunk state scan: 192 blocks, 1 float4/thread -------
__global__ void chunkscan_kernel() {
    int bh   = blockIdx.x >> 2;
    int part = blockIdx.x & 3;
    int idx4 = part * 2048 + threadIdx.x * 4;
    float4 E = make_float4(0.f, 0.f, 0.f, 0.f);
    size_t base = (size_t)bh * NCHUNK * (HEADDIM * DSTATE);
#pragma unroll
    for (int k = 0; k < NCHUNK; k++) {
        float dAk = expf(g_cum[bh * SEQLEN + k * LC + (LC - 1)]);
        size_t off = base + (size_t)k * (HEADDIM * DSTATE) + idx4;
        *(float4*)(g_P + off) = E;
        float4 s = *(const float4*)(g_S + off);
        E.x = s.x + dAk * E.x;
        E.y = s.y + dAk * E.y;
        E.z = s.z + dAk * E.z;
        E.w = s.w + dAk * E.w;
    }
}

// ---------------- inter-chunk Y + gating + bf16 split -----------------------
#define SB_STRIDE 132
#define SMEMD_FLOATS (2*64*SB_STRIDE + 64)
__global__ __launch_bounds__(256)
void inter_gate_kernel() {
    extern __shared__ float sm[];
    float* sC   = sm;
    float* sP   = sC + 64 * SB_STRIDE;
    float* scum = sP + 64 * SB_STRIDE;

    int g  = blockIdx.x;
    int c  = g & (NCHUNK - 1);
    int bh = g >> 3;
    int h  = bh % NHEADS;
    int b  = bh / NHEADS;
    int tid = threadIdx.x;
    int m0 = b * SEQLEN + c * LC;
    size_t pbase = (size_t)(bh * NCHUNK + c) * (HEADDIM * DSTATE);

    for (int i = tid; i < 64 * 32; i += 256) {
        int r = i >> 5, q = i & 31;
        *(float4*)(sC + r * SB_STRIDE + q * 4) =
            *(const float4*)(g_Cm + (size_t)(m0 + r) * DSTATE + q * 4);
        *(float4*)(sP + r * SB_STRIDE + q * 4) =
            *(const float4*)(g_P + pbase + r * DSTATE + q * 4);
    }
    if (tid < 64) scum[tid] = g_cum[bh * SEQLEN + c * LC + tid];
    __syncthreads();

    int tx = tid & 15, ty = tid >> 4;
    int rot = (tid & 15) * 4;
    float acc[4][4] = {};
    for (int n0_ = 0; n0_ < 128; n0_ += 4) {
        int n = (n0_ + rot) & 127;
        float4 a4[4], b4[4];
#pragma unroll
        for (int i = 0; i < 4; i++) a4[i] = *(float4*)(sC + (ty * 4 + i) * SB_STRIDE + n);
#pragma unroll
        for (int j = 0; j < 4; j++) b4[j] = *(float4*)(sP + (tx * 4 + j) * SB_STRIDE + n);
#pragma unroll
        for (int i = 0; i < 4; i++)
#pragma unroll
            for (int j = 0; j < 4; j++)
                acc[i][j] += a4[i].x * b4[j].x + a4[i].y * b4[j].y
                           + a4[i].z * b4[j].z + a4[i].w * b4[j].w;
    }
#pragma unroll
    for (int i = 0; i < 4; i++) {
        int t_ = ty * 4 + i;
        float dec = expf(scum[t_]);
#pragma unroll
        for (int j = 0; j < 4; j++) {
            int p_ = tx * 4 + j;
            size_t mi = (size_t)(m0 + t_) * DINNER + h * HEADDIM + p_;
            float y = g_Y0[mi] + dec * acc[i][j];
            size_t zo = (size_t)(m0 + t_) * DINPROJ + h * HEADDIM + p_;
            float z = g_zx[zo] + g_zx[zo + ZXPLANE];
            float gv = y * (z / (1.f + expf(-z)));
            __nv_bfloat16 hb, lb;
            split1(gv, hb, lb);
            g_ghi[mi] = hb;
            g_glo[mi] = lb;
        }
    }
}

// ---------------- launch ----------------------------------------------------
extern "C" void kernel_launch(void* const* d_in, const int* in_sizes, int n_in,
                              void* d_out, int out_size) {
    const float* u       = (const float*)d_in[0];
    const float* W_in    = (const float*)d_in[1];
    const float* conv_w  = (const float*)d_in[2];
    const float* conv_b  = (const float*)d_in[3];
    const float* dt_bias = (const float*)d_in[4];
    const float* A_log   = (const float*)d_in[5];
    const float* D_param = (const float*)d_in[6];
    const float* W_out   = (const float*)d_in[7];
    float* out = (float*)d_out;

    float *zx, *pp;
    cudaGetSymbolAddress((void**)&zx, g_zx);
    cudaGetSymbolAddress((void**)&pp, g_pp);
    __nv_bfloat16 *uhi, *ulo, *wih, *wil, *ghi, *glo, *woh, *wol;
    cudaGetSymbolAddress((void**)&uhi, g_uhi);  cudaGetSymbolAddress((void**)&ulo, g_ulo);
    cudaGetSymbolAddress((void**)&wih, g_wih);  cudaGetSymbolAddress((void**)&wil, g_wil);
    cudaGetSymbolAddress((void**)&ghi, g_ghi);  cudaGetSymbolAddress((void**)&glo, g_glo);
    cudaGetSymbolAddress((void**)&woh, g_woh);  cudaGetSymbolAddress((void**)&wol, g_wol);

    static bool attr_done = false;
    if (!attr_done) {
        cudaFuncSetAttribute(intra_tc, cudaFuncAttributeMaxDynamicSharedMemorySize,
                             INTRA_SMEM);
        cudaFuncSetAttribute(inter_gate_kernel, cudaFuncAttributeMaxDynamicSharedMemorySize,
                             SMEMD_FLOATS * sizeof(float));
        cudaFuncSetAttribute(mma_gemm, cudaFuncAttributeMaxDynamicSharedMemorySize,
                             GNSTAGE * GSTAGE_BYTES);
        attr_done = true;
    }
    const int TC_SMEM = GNSTAGE * GSTAGE_BYTES;  // 98304

    // 0. fused vectorized split of u, W_in, W_out
    {
        int ntot4 = (N_U + N_WI + N_WO) / 4;
        split_all_kernel<<<(ntot4 + 255) / 256, 256>>>(u, W_in, W_out);
    }
    // 1. in-projection, split-K x2 (consumers fuse the reduction)
    {
        dim3 grid(NPAD_IN / 128, MROWS / 128, INSPLIT);
        mma_gemm<<<grid, 256, TC_SMEM>>>(uhi, ulo, wih, wil, zx,
                                         DMODEL, DINPROJ, DINPROJ, (size_t)ZXPLANE);
    }
    // 2+3. fused scalar conv+silu AND dt+cumsum (block-range split)
    conv_dt_kernel<<<CONV_BLOCKS + DT_BLOCKS, 256>>>(conv_w, conv_b, dt_bias, A_log);
    // 4. intra-chunk (tensor cores)
    intra_tc<<<NBH * NCHUNK, 256, INTRA_SMEM>>>(D_param);
    // 5. inter-chunk state scan
    chunkscan_kernel<<<NBH * 4, 512>>>();
    // 6. inter-chunk Y + gating
    inter_gate_kernel<<<NBH * NCHUNK, 256, SMEMD_FLOATS * sizeof(float)>>>();
    // 7. out-projection, split-K x6, then reduce
    {
        dim3 grid(DMODEL / 128, MROWS / 128, NSPLIT);
        mma_gemm<<<grid, 256, TC_SMEM>>>(ghi, glo, woh, wol, pp,
                                         DINNER, DMODEL, DMODEL,
                                         (size_t)MROWS * DMODEL);
        reduce_kernel<<<(MROWS * DMODEL / 4 + 255) / 256, 256>>>(out);
    }
}

// round 17
// speedup vs baseline: 1.1501x; 1.0242x over previous
#include <cuda_runtime.h>
#include <cuda_bf16.h>
#include <math.h>
#include <cstdint>

#define BATCH   2
#define SEQLEN  512
#define DMODEL  768
#define DINNER  1536
#define NHEADS  24
#define HEADDIM 64
#define DSTATE  128
#define CONVDIM 1792
#define DINPROJ 3352
#define MROWS   (BATCH*SEQLEN)  // 1024
#define LC      64
#define NCHUNK  (SEQLEN/LC)     // 8
#define NBH     (BATCH*NHEADS)  // 48
#define NPAD_IN 3456
#define NSPLIT  6
#define ZXPLANE (MROWS * DINPROJ)
#define INSPLIT 2

// ---------------- scratch ---------------------------------------------------
__device__ float g_zx [INSPLIT * ZXPLANE];
__device__ float g_X  [MROWS * DINNER];
__device__ float g_Bm [MROWS * DSTATE];
__device__ float g_Cm [MROWS * DSTATE];
__device__ float g_dtv[NBH * SEQLEN];
__device__ float g_cum[NBH * SEQLEN];
__device__ float g_Y0 [MROWS * DINNER];
__device__ float g_S  [NBH * NCHUNK * HEADDIM * DSTATE];
__device__ float g_P  [NBH * NCHUNK * HEADDIM * DSTATE];
__device__ float g_pp [NSPLIT * MROWS * DMODEL];

__device__ __align__(256) __nv_bfloat16 g_uhi[MROWS * DMODEL],   g_ulo[MROWS * DMODEL];
__device__ __align__(256) __nv_bfloat16 g_wih[NPAD_IN * DMODEL], g_wil[NPAD_IN * DMODEL];
__device__ __align__(256) __nv_bfloat16 g_ghi[MROWS * DINNER],   g_glo[MROWS * DINNER];
__device__ __align__(256) __nv_bfloat16 g_woh[DMODEL * DINNER],  g_wol[DMODEL * DINNER];
// bf16 hi/lo copies of conv outputs B and C (k-major), produced by conv_dt
__device__ __align__(256) __nv_bfloat16 g_Bbh[MROWS * DSTATE], g_Bbl[MROWS * DSTATE];
__device__ __align__(256) __nv_bfloat16 g_Cbh[MROWS * DSTATE], g_Cbl[MROWS * DSTATE];

// ================= helpers =================================================
__device__ __forceinline__ uint32_t smem_u32(const void* p) {
    uint32_t a;
    asm("{ .reg .u64 t; cvta.to.shared.u64 t, %1; cvt.u32.u64 %0, t; }"
        : "=r"(a) : "l"(p));
    return a;
}
__device__ __forceinline__ void ldsm_x4(uint32_t* r, uint32_t addr) {
    asm volatile("ldmatrix.sync.aligned.m8n8.x4.shared.b16 {%0,%1,%2,%3}, [%4];"
                 : "=r"(r[0]), "=r"(r[1]), "=r"(r[2]), "=r"(r[3]) : "r"(addr));
}
__device__ __forceinline__ void ldsm_x2(uint32_t* r, uint32_t addr) {
    asm volatile("ldmatrix.sync.aligned.m8n8.x2.shared.b16 {%0,%1}, [%2];"
                 : "=r"(r[0]), "=r"(r[1]) : "r"(addr));
}
__device__ __forceinline__ void mma_bf16(float* c, const uint32_t* a, const uint32_t* b) {
    asm volatile(
        "mma.sync.aligned.m16n8k16.row.col.f32.bf16.bf16.f32 "
        "{%0,%1,%2,%3}, {%4,%5,%6,%7}, {%8,%9}, {%0,%1,%2,%3};"
        : "+f"(c[0]), "+f"(c[1]), "+f"(c[2]), "+f"(c[3])
        : "r"(a[0]), "r"(a[1]), "r"(a[2]), "r"(a[3]), "r"(b[0]), "r"(b[1]));
}
__device__ __forceinline__ void split1(float v, __nv_bfloat16& h, __nv_bfloat16& l) {
    h = __float2bfloat16(v);
    l = __float2bfloat16(v - __bfloat162float(h));
}
__device__ __forceinline__ void split2(float2 v, uint32_t& hi2, uint32_t& lo2) {
    __nv_bfloat16 h0, l0, h1, l1;
    split1(v.x, h0, l0);
    split1(v.y, h1, l1);
    __nv_bfloat162 H, L;
    H.x = h0; H.y = h1; L.x = l0; L.y = l1;
    hi2 = *(uint32_t*)&H;
    lo2 = *(uint32_t*)&L;
}
__device__ __forceinline__ void split4_store(float4 v, __nv_bfloat16* hi, __nv_bfloat16* lo, int j) {
    uint32_t h01, l01, h23, l23;
    split2(make_float2(v.x, v.y), h01, l01);
    split2(make_float2(v.z, v.w), h23, l23);
    uint2 H = make_uint2(h01, h23), L = make_uint2(l01, l23);
    *(uint2*)(hi + j) = H;
    *(uint2*)(lo + j) = L;
}

// ================= fused vectorized split of u, W_in(+pad), W_out ==========
#define N_U  (MROWS * DMODEL)
#define N_WI (NPAD_IN * DMODEL)
#define N_WIS (DINPROJ * DMODEL)
#define N_WO (DMODEL * DINNER)
__global__ void split_all_kernel(const float* __restrict__ u,
                                 const float* __restrict__ W_in,
                                 const float* __restrict__ W_out) {
    int i4 = blockIdx.x * blockDim.x + threadIdx.x;
    int i = i4 * 4;
    if (i < N_U) {
        float4 v = *(const float4*)(u + i);
        split4_store(v, g_uhi, g_ulo, i);
    } else if (i < N_U + N_WI) {
        int j = i - N_U;
        float4 v = (j < N_WIS) ? *(const float4*)(W_in + j)
                               : make_float4(0.f, 0.f, 0.f, 0.f);
        split4_store(v, g_wih, g_wil, j);
    } else if (i < N_U + N_WI + N_WO) {
        int j = i - N_U - N_WI;
        float4 v = *(const float4*)(W_out + j);
        split4_store(v, g_woh, g_wol, j);
    }
}

// ================= mma.sync bf16 GEMM, 4-stage pipeline ====================
#define GSTRIDE 24
#define GOP_BYTES (128 * GSTRIDE * 2)      // 6144
#define GSTAGE_BYTES (4 * GOP_BYTES)       // 24576
#define GNSTAGE 4
__global__ __launch_bounds__(256, 2)
void mma_gemm(const __nv_bfloat16* __restrict__ Ahi, const __nv_bfloat16* __restrict__ Alo,
              const __nv_bfloat16* __restrict__ Bhi, const __nv_bfloat16* __restrict__ Blo,
              float* __restrict__ C, int Ktot, int Nact, int ldc, size_t csplit) {
    extern __shared__ char smx[];
    uint32_t sb = smem_u32(smx);
    int tid  = threadIdx.x;
    int lane = tid & 31, wid = tid >> 5;
    int wm = wid >> 2, wn = wid & 3;
    int m0 = blockIdx.y * 128, n0 = blockIdx.x * 128;
    int nsp  = gridDim.z;
    int Klen = Ktot / nsp;
    int k0   = blockIdx.z * Klen;
    float* Cp = C + (size_t)blockIdx.z * csplit;
    const int KT = Klen / 16;

    const __nv_bfloat16* ptrs[4] = {Ahi, Alo, Bhi, Blo};
    int rbase[4] = {m0, m0, n0, n0};

    auto load_stage = [&](int kt, int s) {
        uint32_t sbase = sb + s * GSTAGE_BYTES;
#pragma unroll
        for (int op = 0; op < 4; op++) {
            int r = tid >> 1, hf = tid & 1;
            const void* g = ptrs[op] + (size_t)(rbase[op] + r) * Ktot + k0 + kt * 16 + hf * 8;
            uint32_t d = sbase + op * GOP_BYTES + (r * GSTRIDE + hf * 8) * 2;
            asm volatile("cp.async.cg.shared.global [%0], [%1], 16;" :: "r"(d), "l"(g));
        }
        asm volatile("cp.async.commit_group;");
    };

    float acc[4][4][4];
#pragma unroll
    for (int i = 0; i < 4; i++)
#pragma unroll
        for (int j = 0; j < 4; j++)
#pragma unroll
            for (int q = 0; q < 4; q++) acc[i][j][q] = 0.f;

    load_stage(0, 0);
    load_stage(1, 1);
    load_stage(2, 2);

    for (int kt = 0; kt < KT; kt++) {
        asm volatile("cp.async.wait_group 2;");
        __syncthreads();

        uint32_t st = sb + (kt & 3) * GSTAGE_BYTES;
        uint32_t ah[4][4], al[4][4], bh[4][2], bl[4][2];
        int arow = wm * 64 + (lane & 15);
        int acol = (lane >> 4) * 8;
#pragma unroll
        for (int i = 0; i < 4; i++) {
            uint32_t off = ((arow + i * 16) * GSTRIDE + acol) * 2;
            ldsm_x4(ah[i], st + off);
            ldsm_x4(al[i], st + GOP_BYTES + off);
        }
        int brow = wn * 32 + (lane & 7);
        int bcol = ((lane >> 3) & 1) * 8;
#pragma unroll
        for (int j = 0; j < 4; j++) {
            uint32_t off = ((brow + j * 8) * GSTRIDE + bcol) * 2;
            ldsm_x2(bh[j], st + 2 * GOP_BYTES + off);
            ldsm_x2(bl[j], st + 3 * GOP_BYTES + off);
        }
#pragma unroll
        for (int i = 0; i < 4; i++)
#pragma unroll
            for (int j = 0; j < 4; j++) {
                mma_bf16(acc[i][j], ah[i], bh[j]);
                mma_bf16(acc[i][j], ah[i], bl[j]);
                mma_bf16(acc[i][j], al[i], bh[j]);
            }

        if (kt + 3 < KT) load_stage(kt + 3, (kt + 3) & 3);
        else             asm volatile("cp.async.commit_group;");
    }

    int r0 = m0 + wm * 64 + (lane >> 2);
    int c0 = n0 + wn * 32 + (lane & 3) * 2;
#pragma unroll
    for (int i = 0; i < 4; i++) {
#pragma unroll
        for (int j = 0; j < 4; j++) {
            int rr = r0 + i * 16;
            int cc = c0 + j * 8;
            if (cc < Nact)     Cp[(size_t)rr * ldc + cc]           = acc[i][j][0];
            if (cc + 1 < Nact) Cp[(size_t)rr * ldc + cc + 1]       = acc[i][j][1];
            if (cc < Nact)     Cp[(size_t)(rr + 8) * ldc + cc]     = acc[i][j][2];
            if (cc + 1 < Nact) Cp[(size_t)(rr + 8) * ldc + cc + 1] = acc[i][j][3];
        }
    }
}

// ---------------- reduce NSPLIT partials -> out -----------------------------
__global__ void reduce_kernel(float* __restrict__ out) {
    int i = blockIdx.x * blockDim.x + threadIdx.x;
    const int n4 = MROWS * DMODEL / 4;
    if (i >= n4) return;
    float4 r = make_float4(0.f, 0.f, 0.f, 0.f);
#pragma unroll
    for (int s = 0; s < NSPLIT; s++) {
        float4 a = *(const float4*)(g_pp + (size_t)s * MROWS * DMODEL + i * 4);
        r.x += a.x; r.y += a.y; r.z += a.z; r.w += a.w;
    }
    *(float4*)(out + i * 4) = r;
}

// ---------------- fused: scalar conv+SiLU (+B/C bf16 split)  AND  dt/cumsum -
#define CONV_BLOCKS ((MROWS * CONVDIM + 255) / 256)   // 7168
#define DT_BLOCKS (NBH * NCHUNK / 4)                  // 96
__global__ void conv_dt_kernel(const float* __restrict__ conv_w,
                               const float* __restrict__ conv_b,
                               const float* __restrict__ dt_bias,
                               const float* __restrict__ A_log) {
    if (blockIdx.x < CONV_BLOCKS) {
        int idx = blockIdx.x * 256 + threadIdx.x;
        if (idx >= MROWS * CONVDIM) return;
        int c = idx % CONVDIM;
        int m = idx / CONVDIM;
        int t = m % SEQLEN;
        float s = conv_b[c];
#pragma unroll
        for (int k = 0; k < 4; k++) {
            int tt = t - 3 + k;
            if (tt >= 0) {
                size_t o = (size_t)(m - 3 + k) * DINPROJ + DINNER + c;
                s += (g_zx[o] + g_zx[o + ZXPLANE]) * conv_w[c * 4 + k];
            }
        }
        float v = s / (1.f + expf(-s));
        if (c < DINNER) {
            g_X[m * DINNER + c] = v;
        } else if (c < DINNER + DSTATE) {
            int n = c - DINNER;
            g_Bm[m * DSTATE + n] = v;
            __nv_bfloat16 hh, ll;
            split1(v, hh, ll);
            g_Bbh[m * DSTATE + n] = hh;
            g_Bbl[m * DSTATE + n] = ll;
        } else {
            int n = c - DINNER - DSTATE;
            g_Cm[m * DSTATE + n] = v;
            __nv_bfloat16 hh, ll;
            split1(v, hh, ll);
            g_Cbh[m * DSTATE + n] = hh;
            g_Cbl[m * DSTATE + n] = ll;
        }
    } else {
        __shared__ float w0tot[4];
        int sub = threadIdx.x >> 6;
        int t   = threadIdx.x & 63;
        int g   = (blockIdx.x - CONV_BLOCKS) * 4 + sub;
        int c   = g & (NCHUNK - 1);
        int bh  = g >> 3;
        int h   = bh % NHEADS;
        int b   = bh / NHEADS;
        int m   = b * SEQLEN + c * LC + t;

        size_t o = (size_t)m * DINPROJ + DINNER + CONVDIM + h;
        float x   = g_zx[o] + g_zx[o + ZXPLANE] + dt_bias[h];
        float dtv = (x > 20.f) ? x : log1pf(expf(x));
        float a   = -expf(A_log[h]) * dtv;

        float sc = a;
#pragma unroll
        for (int o2 = 1; o2 < 32; o2 <<= 1) {
            float v = __shfl_up_sync(0xffffffffu, sc, o2);
            if ((t & 31) >= o2) sc += v;
        }
        if (t == 31) w0tot[sub] = sc;
        __syncthreads();
        if (t >= 32) sc += w0tot[sub];

        int idx = bh * SEQLEN + c * LC + t;
        g_dtv[idx] = dtv;
        g_cum[idx] = sc;
    }
}

// ---------------- intra-chunk kernel (tensor cores) ------------------------
#define OFF_SCUM 0
#define OFF_SDT  256
#define OFF_SW   512
#define PLANE128 (64*136*2)     // 17408
#define PLANE64  (64*72*2)      // 9216
#define PLANE128T (128*72*2)    // 18432
#define OFF_XTHI 768
#define OFF_XTLO (OFF_XTHI + PLANE64)
#define OFF_BIG  (OFF_XTLO + PLANE64)        // 19200
#define OFF_CHI  (OFF_BIG)
#define OFF_CLO  (OFF_CHI + PLANE128)
#define OFF_BHI  (OFF_CLO + PLANE128)
#define OFF_BLO  (OFF_BHI + PLANE128)
#define OFF_GHI  (OFF_BIG)
#define OFF_GLO  (OFF_GHI + PLANE64)
#define OFF_BWHI (OFF_GLO + PLANE64)
#define OFF_BWLO (OFF_BWHI + PLANE128T)
#define INTRA_SMEM (OFF_BIG + 4*PLANE128)    // 88832
__global__ __launch_bounds__(256, 2)
void intra_tc(const float* __restrict__ D_param) {
    extern __shared__ char smc[];
    uint32_t sb = smem_u32(smc);
    float* scum = (float*)(smc + OFF_SCUM);
    float* sdt  = (float*)(smc + OFF_SDT);
    float* sw   = (float*)(smc + OFF_SW);
    __nv_bfloat16* Xthi = (__nv_bfloat16*)(smc + OFF_XTHI);
    __nv_bfloat16* Xtlo = (__nv_bfloat16*)(smc + OFF_XTLO);
    __nv_bfloat16* Bwhi = (__nv_bfloat16*)(smc + OFF_BWHI);
    __nv_bfloat16* Bwlo = (__nv_bfloat16*)(smc + OFF_BWLO);
    __nv_bfloat16* Ghi  = (__nv_bfloat16*)(smc + OFF_GHI);
    __nv_bfloat16* Glo  = (__nv_bfloat16*)(smc + OFF_GLO);

    int g  = blockIdx.x;
    int c  = g & (NCHUNK - 1);
    int bh = g >> 3;
    int h  = bh % NHEADS;
    int b  = bh / NHEADS;
    int tid = threadIdx.x;
    int lane = tid & 31, wid = tid >> 5;
    int m0 = b * SEQLEN + c * LC;

    // async copy bf16 C/B planes (pre-split by conv) into stride-136 smem
    {
        const __nv_bfloat16* srcs[4] = {g_Cbh, g_Cbl, g_Bbh, g_Bbl};
        const uint32_t offs[4] = {OFF_CHI, OFF_CLO, OFF_BHI, OFF_BLO};
#pragma unroll
        for (int pl = 0; pl < 4; pl++) {
            for (int i = tid; i < 64 * 16; i += 256) {
                int r = i >> 4, ch = i & 15;
                const void* gp = srcs[pl] + (size_t)(m0 + r) * DSTATE + ch * 8;
                uint32_t d = sb + offs[pl] + (r * 136 + ch * 8) * 2;
                asm volatile("cp.async.cg.shared.global [%0], [%1], 16;"
                             :: "r"(d), "l"(gp));
            }
        }
        asm volatile("cp.async.commit_group;");
    }
    if (tid < 64) {
        scum[tid] = g_cum[bh * SEQLEN + c * LC + tid];
        sdt[tid]  = g_dtv[bh * SEQLEN + c * LC + tid];
    }
    // X transpose conversion — consecutive threads take consecutive t_
    for (int i = tid; i < 64 * 16; i += 256) {
        int t_ = i & 63, p4 = (i >> 6) * 4;
        float4 v = *(const float4*)(g_X + (size_t)(m0 + t_) * DINNER + h * HEADDIM + p4);
        float vv[4] = {v.x, v.y, v.z, v.w};
#pragma unroll
        for (int e = 0; e < 4; e++) {
            __nv_bfloat16 hh, ll;
            split1(vv[e], hh, ll);
            Xthi[(p4 + e) * 72 + t_] = hh;
            Xtlo[(p4 + e) * 72 + t_] = ll;
        }
    }
    asm volatile("cp.async.wait_group 0;");
    __syncthreads();
    if (tid < 64) sw[tid] = expf(scum[63] - scum[tid]) * sdt[tid];
    __syncthreads();

    int wm = wid & 3, wn = wid >> 2;
    int brow8 = ((lane >> 4) & 1) * 8 + (lane & 7);
    int bcolb = ((lane >> 3) & 1) * 8;

    // ---- stage 1: G0 = C . B^T ----
    float acc1[4][4] = {};
    {
        for (int kk = 0; kk < 8; kk++) {
            uint32_t ah[4], al[4], bh2[4][2], bl2[4][2];
            int arow = wm * 16 + (lane & 15);
            int acol = (lane >> 4) * 8 + kk * 16;
            ldsm_x4(ah, sb + OFF_CHI + (arow * 136 + acol) * 2);
            ldsm_x4(al, sb + OFF_CLO + (arow * 136 + acol) * 2);
            int bcol = bcolb + kk * 16;
#pragma unroll
            for (int j2 = 0; j2 < 2; j2++) {
                int br = wn * 32 + j2 * 16 + brow8;
                ldsm_x4(&bh2[2 * j2][0], sb + OFF_BHI + (br * 136 + bcol) * 2);
                ldsm_x4(&bl2[2 * j2][0], sb + OFF_BLO + (br * 136 + bcol) * 2);
            }
#pragma unroll
            for (int j = 0; j < 4; j++) {
                mma_bf16(acc1[j], ah, bh2[j]);
                mma_bf16(acc1[j], ah, bl2[j]);
                mma_bf16(acc1[j], al, bh2[j]);
            }
        }
    }
    __syncthreads();   // C/B planes dead; reuse for G and Bwt

    {
        int tr = wm * 16 + (lane >> 2);
#pragma unroll
        for (int j = 0; j < 4; j++) {
            int sc0 = wn * 32 + j * 8 + (lane & 3) * 2;
#pragma unroll
            for (int hlf = 0; hlf < 2; hlf++) {
                int t_ = tr + hlf * 8;
#pragma unroll
                for (int e = 0; e < 2; e++) {
                    int s_ = sc0 + e;
                    float wgt = (s_ <= t_) ? expf(scum[t_] - scum[s_]) * sdt[s_] : 0.f;
                    float gv = acc1[j][hlf * 2 + e] * wgt;
                    __nv_bfloat16 hh, ll;
                    split1(gv, hh, ll);
                    Ghi[t_ * 72 + s_] = hh;
                    Glo[t_ * 72 + s_] = ll;
                }
            }
        }
    }
    // Bwt[n][s] = w[s]*B[s][n] — consecutive threads take consecutive s_
    for (int i = tid; i < 64 * 32; i += 256) {
        int s_ = i & 63, n4 = (i >> 6) * 4;
        float4 v = *(const float4*)(g_Bm + (size_t)(m0 + s_) * DSTATE + n4);
        float w = sw[s_];
        float vv[4] = {v.x * w, v.y * w, v.z * w, v.w * w};
#pragma unroll
        for (int e = 0; e < 4; e++) {
            __nv_bfloat16 hh, ll;
            split1(vv[e], hh, ll);
            Bwhi[(n4 + e) * 72 + s_] = hh;
            Bwlo[(n4 + e) * 72 + s_] = ll;
        }
    }
    __syncthreads();

    // ---- stage 2: Y = G . Xt^T (+ D*x) ----
    {
        float acc[4][4] = {};
        for (int kk = 0; kk < 4; kk++) {
            uint32_t ah[4], al[4], bh2[4][2], bl2[4][2];
            int arow = wm * 16 + (lane & 15);
            int acol = (lane >> 4) * 8 + kk * 16;
            ldsm_x4(ah, sb + OFF_GHI + (arow * 72 + acol) * 2);
            ldsm_x4(al, sb + OFF_GLO + (arow * 72 + acol) * 2);
            int bcol = bcolb + kk * 16;
#pragma unroll
            for (int j2 = 0; j2 < 2; j2++) {
                int br = wn * 32 + j2 * 16 + brow8;
                ldsm_x4(&bh2[2 * j2][0], sb + OFF_XTHI + (br * 72 + bcol) * 2);
                ldsm_x4(&bl2[2 * j2][0], sb + OFF_XTLO + (br * 72 + bcol) * 2);
            }
#pragma unroll
            for (int j = 0; j < 4; j++) {
                mma_bf16(acc[j], ah, bh2[j]);
                mma_bf16(acc[j], ah, bl2[j]);
                mma_bf16(acc[j], al, bh2[j]);
            }
        }
        float Dp = D_param[h];
        int tr = wm * 16 + (lane >> 2);
#pragma unroll
        for (int j = 0; j < 4; j++) {
            int p0 = wn * 32 + j * 8 + (lane & 3) * 2;
#pragma unroll
            for (int hlf = 0; hlf < 2; hlf++) {
                int t_ = tr + hlf * 8;
#pragma unroll
                for (int e = 0; e < 2; e++) {
                    int p_ = p0 + e;
                    float xv = __bfloat162float(Xthi[p_ * 72 + t_])
                             + __bfloat162float(Xtlo[p_ * 72 + t_]);
                    g_Y0[(size_t)(m0 + t_) * DINNER + h * HEADDIM + p_] =
                        acc[j][hlf * 2 + e] + Dp * xv;
                }
            }
        }
    }

    // ---- stage 3: S = Xt . Bwt^T ----
    {
        float acc[8][4] = {};
        for (int kk = 0; kk < 4; kk++) {
            uint32_t ah[4], al[4], bh2[8][2], bl2[8][2];
            int arow = wm * 16 + (lane & 15);
            int acol = (lane >> 4) * 8 + kk * 16;
            ldsm_x4(ah, sb + OFF_XTHI + (arow * 72 + acol) * 2);
            ldsm_x4(al, sb + OFF_XTLO + (arow * 72 + acol) * 2);
            int bcol = bcolb + kk * 16;
#pragma unroll
            for (int j2 = 0; j2 < 4; j2++) {
                int br = wn * 64 + j2 * 16 + brow8;
                ldsm_x4(&bh2[2 * j2][0], sb + OFF_BWHI + (br * 72 + bcol) * 2);
                ldsm_x4(&bl2[2 * j2][0], sb + OFF_BWLO + (br * 72 + bcol) * 2);
            }
#pragma unroll
            for (int j = 0; j < 8; j++) {
                mma_bf16(acc[j], ah, bh2[j]);
                mma_bf16(acc[j], ah, bl2[j]);
                mma_bf16(acc[j], al, bh2[j]);
            }
        }
        size_t base = (size_t)(bh * NCHUNK + c) * (HEADDIM * DSTATE);
        int pr = wm * 16 + (lane >> 2);
#pragma unroll
        for (int j = 0; j < 8; j++) {
            int n0_ = wn * 64 + j * 8 + (lane & 3) * 2;
#pragma unroll
            for (int hlf = 0; hlf < 2; hlf++) {
                int p_ = pr + hlf * 8;
#pragma unroll
                for (int e = 0; e < 2; e++) {
                    g_S[base + p_ * DSTATE + n0_ + e] = acc[j][hlf * 2 + e];
                }
            }
        }
    }
}

// ---------------- inter-chunk state scan: 192 blocks, 1 float4/thread -------
__global__ void chunkscan_kernel() {
    int bh   = blockIdx.x >> 2;
    int part = blockIdx.x & 3;
    int idx4 = part * 2048 + threadIdx.x * 4;
    float4 E = make_float4(0.f, 0.f, 0.f, 0.f);
    size_t base = (size_t)bh * NCHUNK * (HEADDIM * DSTATE);
#pragma unroll
    for (int k = 0; k < NCHUNK; k++) {
        float dAk = expf(g_cum[bh * SEQLEN + k * LC + (LC - 1)]);
        size_t off = base + (size_t)k * (HEADDIM * DSTATE) + idx4;
        *(float4*)(g_P + off) = E;
        float4 s = *(const float4*)(g_S + off);
        E.x = s.x + dAk * E.x;
        E.y = s.y + dAk * E.y;
        E.z = s.z + dAk * E.z;
        E.w = s.w + dAk * E.w;
    }
}

// ---------------- inter-chunk Y + gating + bf16 split -----------------------
#define SB_STRIDE 132
#define SMEMD_FLOATS (2*64*SB_STRIDE + 64)
__global__ __launch_bounds__(256)
void inter_gate_kernel() {
    extern __shared__ float sm[];
    float* sC   = sm;
    float* sP   = sC + 64 * SB_STRIDE;
    float* scum = sP + 64 * SB_STRIDE;

    int g  = blockIdx.x;
    int c  = g & (NCHUNK - 1);
    int bh = g >> 3;
    int h  = bh % NHEADS;
    int b  = bh / NHEADS;
    int tid = threadIdx.x;
    int m0 = b * SEQLEN + c * LC;
    size_t pbase = (size_t)(bh * NCHUNK + c) * (HEADDIM * DSTATE);

    for (int i = tid; i < 64 * 32; i += 256) {
        int r = i >> 5, q = i & 31;
        *(float4*)(sC + r * SB_STRIDE + q * 4) =
            *(const float4*)(g_Cm + (size_t)(m0 + r) * DSTATE + q * 4);
        *(float4*)(sP + r * SB_STRIDE + q * 4) =
            *(const float4*)(g_P + pbase + r * DSTATE + q * 4);
    }
    if (tid < 64) scum[tid] = g_cum[bh * SEQLEN + c * LC + tid];
    __syncthreads();

    int tx = tid & 15, ty = tid >> 4;
    int rot = (tid & 15) * 4;
    float acc[4][4] = {};
    for (int n0_ = 0; n0_ < 128; n0_ += 4) {
        int n = (n0_ + rot) & 127;
        float4 a4[4], b4[4];
#pragma unroll
        for (int i = 0; i < 4; i++) a4[i] = *(float4*)(sC + (ty * 4 + i) * SB_STRIDE + n);
#pragma unroll
        for (int j = 0; j < 4; j++) b4[j] = *(float4*)(sP + (tx * 4 + j) * SB_STRIDE + n);
#pragma unroll
        for (int i = 0; i < 4; i++)
#pragma unroll
            for (int j = 0; j < 4; j++)
                acc[i][j] += a4[i].x * b4[j].x + a4[i].y * b4[j].y
                           + a4[i].z * b4[j].z + a4[i].w * b4[j].w;
    }
#pragma unroll
    for (int i = 0; i < 4; i++) {
        int t_ = ty * 4 + i;
        float dec = expf(scum[t_]);
#pragma unroll
        for (int j = 0; j < 4; j++) {
            int p_ = tx * 4 + j;
            size_t mi = (size_t)(m0 + t_) * DINNER + h * HEADDIM + p_;
            float y = g_Y0[mi] + dec * acc[i][j];
            size_t zo = (size_t)(m0 + t_) * DINPROJ + h * HEADDIM + p_;
            float z = g_zx[zo] + g_zx[zo + ZXPLANE];
            float gv = y * (z / (1.f + expf(-z)));
            __nv_bfloat16 hb, lb;
            split1(gv, hb, lb);
            g_ghi[mi] = hb;
            g_glo[mi] = lb;
        }
    }
}

// ---------------- launch ----------------------------------------------------
extern "C" void kernel_launch(void* const* d_in, const int* in_sizes, int n_in,
                              void* d_out, int out_size) {
    const float* u       = (const float*)d_in[0];
    const float* W_in    = (const float*)d_in[1];
    const float* conv_w  = (const float*)d_in[2];
    const float* conv_b  = (const float*)d_in[3];
    const float* dt_bias = (const float*)d_in[4];
    const float* A_log   = (const float*)d_in[5];
    const float* D_param = (const float*)d_in[6];
    const float* W_out   = (const float*)d_in[7];
    float* out = (float*)d_out;

    float *zx, *pp;
    cudaGetSymbolAddress((void**)&zx, g_zx);
    cudaGetSymbolAddress((void**)&pp, g_pp);
    __nv_bfloat16 *uhi, *ulo, *wih, *wil, *ghi, *glo, *woh, *wol;
    cudaGetSymbolAddress((void**)&uhi, g_uhi);  cudaGetSymbolAddress((void**)&ulo, g_ulo);
    cudaGetSymbolAddress((void**)&wih, g_wih);  cudaGetSymbolAddress((void**)&wil, g_wil);
    cudaGetSymbolAddress((void**)&ghi, g_ghi);  cudaGetSymbolAddress((void**)&glo, g_glo);
    cudaGetSymbolAddress((void**)&woh, g_woh);  cudaGetSymbolAddress((void**)&wol, g_wol);

    static bool attr_done = false;
    if (!attr_done) {
        cudaFuncSetAttribute(intra_tc, cudaFuncAttributeMaxDynamicSharedMemorySize,
                             INTRA_SMEM);
        cudaFuncSetAttribute(inter_gate_kernel, cudaFuncAttributeMaxDynamicSharedMemorySize,
                             SMEMD_FLOATS * sizeof(float));
        cudaFuncSetAttribute(mma_gemm, cudaFuncAttributeMaxDynamicSharedMemorySize,
                             GNSTAGE * GSTAGE_BYTES);
        attr_done = true;
    }
    const int TC_SMEM = GNSTAGE * GSTAGE_BYTES;  // 98304

    // 0. fused vectorized split of u, W_in, W_out
    {
        int ntot4 = (N_U + N_WI + N_WO) / 4;
        split_all_kernel<<<(ntot4 + 255) / 256, 256>>>(u, W_in, W_out);
    }
    // 1. in-projection, split-K x2 (consumers fuse the reduction)
    {
        dim3 grid(NPAD_IN / 128, MROWS / 128, INSPLIT);
        mma_gemm<<<grid, 256, TC_SMEM>>>(uhi, ulo, wih, wil, zx,
                                         DMODEL, DINPROJ, DINPROJ, (size_t)ZXPLANE);
    }
    // 2+3. fused conv+silu (+B/C bf16 split) AND dt+cumsum
    conv_dt_kernel<<<CONV_BLOCKS + DT_BLOCKS, 256>>>(conv_w, conv_b, dt_bias, A_log);
    // 4. intra-chunk (tensor cores, cp.async C/B staging)
    intra_tc<<<NBH * NCHUNK, 256, INTRA_SMEM>>>(D_param);
    // 5. inter-chunk state scan
    chunkscan_kernel<<<NBH * 4, 512>>>();
    // 6. inter-chunk Y + gating
    inter_gate_kernel<<<NBH * NCHUNK, 256, SMEMD_FLOATS * sizeof(float)>>>();
    // 7. out-projection, split-K x6, then reduce
    {
        dim3 grid(DMODEL / 128, MROWS / 128, NSPLIT);
        mma_gemm<<<grid, 256, TC_SMEM>>>(ghi, glo, woh, wol, pp,
                                         DINNER, DMODEL, DMODEL,
                                         (size_t)MROWS * DMODEL);
        reduce_kernel<<<(MROWS * DMODEL / 4 + 255) / 256, 256>>>(out);
    }
}